// round 7
// baseline (speedup 1.0000x reference)
#include <cuda_runtime.h>
#include <cuda_fp16.h>
#include <cstdint>

#define BB 4
#define CC 64
#define HH 48
#define WW 64
#define NN (HH*WW)        // 3072
#define BM 128
#define BN 128
#define NTILE (NN/BM)     // 24
#define LDK 72            // smem row stride in halves (144B, 16B-aligned, ldmatrix conflict-free)
#define THR 3.2e-3f       // rigorous fp16-approx error bound (2*(2^-10 + 2^-11) + margin)

// ---------------- device scratch ----------------
__device__ float g_srcT[BB*NN*CC];
__device__ float g_tgtT[BB*NN*CC];
__device__ float g_sd[BB*NN*CC];     // exact f32 descriptors
__device__ float g_td[BB*NN*CC];
__device__ __half g_sdh[BB*NN*CC];   // fp16(x)
__device__ __half g_tdh[BB*NN*CC];
__device__ __half g_D[(size_t)BB*NN*NN];   // approx dot matrix, fp16 (75.5MB)
__device__ unsigned long long g_row_all[BB*NN];
__device__ unsigned long long g_row_un [BB*NN];
__device__ unsigned long long g_col_all[BB*NN];
__device__ unsigned long long g_col_un [BB*NN];
__device__ float g_acc[2];

// ---------------- key packing: argmax(dot), first-index tie-break ----------------
__device__ __forceinline__ unsigned long long make_key(float f, int idx) {
    unsigned u = __float_as_uint(f);
    u = (u & 0x80000000u) ? ~u : (u | 0x80000000u);
    return ((unsigned long long)u << 32) | (unsigned)(0xFFFFFFFFu - (unsigned)idx);
}
__device__ __forceinline__ float key_dot(unsigned long long k) {
    unsigned u = (unsigned)(k >> 32);
    return (u & 0x80000000u) ? __uint_as_float(u ^ 0x80000000u) : __uint_as_float(~u);
}
__device__ __forceinline__ int key_idx(unsigned long long k) {
    return (int)(0xFFFFFFFFu - (unsigned)(k & 0xFFFFFFFFu));
}
__device__ __forceinline__ float dist_from_dot(float d) {
    d = fminf(fmaxf(d, -1.f), 1.f);
    return sqrtf(fmaxf(2.f - 2.f*d, 0.f));
}
__device__ __forceinline__ float decode_relax(const int* rf) {
    int rv = rf[0];
    return (rv >= 0 && rv < 1000000) ? (float)rv : __int_as_float(rv);
}
__device__ __forceinline__ void ldmatrix_x4(unsigned& r0, unsigned& r1, unsigned& r2,
                                            unsigned& r3, unsigned addr) {
    asm volatile("ldmatrix.sync.aligned.m8n8.x4.shared.b16 {%0,%1,%2,%3}, [%4];"
        : "=r"(r0), "=r"(r1), "=r"(r2), "=r"(r3) : "r"(addr));
}
__device__ __forceinline__ void mma_f16(float* c, unsigned a0, unsigned a1,
                                        unsigned a2, unsigned a3,
                                        unsigned b0, unsigned b1) {
    asm volatile(
        "mma.sync.aligned.m16n8k16.row.col.f32.f16.f16.f32 "
        "{%0,%1,%2,%3}, {%4,%5,%6,%7}, {%8,%9}, {%0,%1,%2,%3};\n"
        : "+f"(c[0]), "+f"(c[1]), "+f"(c[2]), "+f"(c[3])
        : "r"(a0), "r"(a1), "r"(a2), "r"(a3), "r"(b0), "r"(b1));
}
__device__ __forceinline__ float exact_dot(const float* __restrict__ a,
                                           const float* __restrict__ bv) {
    float s = 0.f;
    #pragma unroll 16
    for (int k = 0; k < CC; k++) s = fmaf(a[k], bv[k], s);
    return s;
}

// ---------------- 1. coalesced transpose (B,C,H,W)->(B,H*W,C) + init ----------------
__global__ void transpose_kernel(const float* __restrict__ src, const float* __restrict__ tgt) {
    __shared__ float tile[32][33];
    int arr = blockIdx.z >> 2, b = blockIdx.z & 3;
    const float* in = arr ? tgt : src;
    float* out = arr ? g_tgtT : g_srcT;
    int p0 = blockIdx.x*32, c0 = blockIdx.y*32;
    int tx = threadIdx.x & 31, ty = threadIdx.x >> 5;
    #pragma unroll
    for (int q = 0; q < 4; q++)
        tile[ty + q*8][tx] = in[((size_t)b*CC + c0 + ty + q*8)*NN + p0 + tx];
    __syncthreads();
    #pragma unroll
    for (int q = 0; q < 4; q++)
        out[((size_t)b*NN + p0 + ty + q*8)*CC + c0 + tx] = tile[tx][ty + q*8];
    int gi = ((blockIdx.z*gridDim.y + blockIdx.y)*gridDim.x + blockIdx.x)*256 + threadIdx.x;
    if (gi < BB*NN) {
        g_row_all[gi] = 0ULL; g_row_un[gi] = 0ULL;
        g_col_all[gi] = 0ULL; g_col_un[gi] = 0ULL;
    }
    if (gi < 2) g_acc[gi] = 0.f;
}

// ---------------- 2. bilinear sample + normalize + fp16 ----------------
__global__ void sample_kernel(const float* __restrict__ spn, const float* __restrict__ tpn) {
    int gw   = (blockIdx.x*blockDim.x + threadIdx.x) >> 5;
    int lane = threadIdx.x & 31;
    int b    = gw / (2*NN);
    int rem  = gw - b*2*NN;
    int side = rem / NN;
    int p    = rem - side*NN;

    const float* g = (side ? tpn : spn) + ((size_t)b*NN + p)*2;
    float gx = g[0], gy = g[1];
    const float* img = (side ? g_tgtT : g_srcT) + (size_t)b*NN*CC;

    float x = ((gx + 1.f)*WW - 1.f)*0.5f;
    float y = ((gy + 1.f)*HH - 1.f)*0.5f;
    float x0f = floorf(x), y0f = floorf(y);
    int x0 = (int)x0f, y0 = (int)y0f;
    int x1 = x0 + 1,   y1 = y0 + 1;
    float wx1 = x - x0f, wx0 = 1.f - wx1;
    float wy1 = y - y0f, wy0 = 1.f - wy1;

    float v0 = 0.f, v1 = 0.f;
    #define CORNER(XI, YI, WGT) do { \
        if ((XI) >= 0 && (XI) < WW && (YI) >= 0 && (YI) < HH) { \
            const float* q = img + ((size_t)(YI)*WW + (XI))*CC; \
            v0 += (WGT)*q[lane]; v1 += (WGT)*q[lane+32]; \
        } } while(0)
    CORNER(x0, y0, wx0*wy0);
    CORNER(x1, y0, wx1*wy0);
    CORNER(x0, y1, wx0*wy1);
    CORNER(x1, y1, wx1*wy1);
    #undef CORNER

    float ss = v0*v0 + v1*v1;
    #pragma unroll
    for (int m = 16; m; m >>= 1) ss += __shfl_xor_sync(0xFFFFFFFFu, ss, m);
    float inv = 1.f / fmaxf(sqrtf(ss), 1e-12f);

    size_t base = ((size_t)b*NN + p)*CC;
    float*  outf = (side ? g_td  : g_sd ) + base;
    __half* outh = (side ? g_tdh : g_sdh) + base;
    float s0 = v0*inv, s1 = v1*inv;
    outf[lane]    = s0;
    outf[lane+32] = s1;
    outh[lane]    = __float2half_rn(s0);
    outh[lane+32] = __float2half_rn(s1);
}

// ---------------- 3. fp16 1x tensor GEMM + approx argmax + D store ----------------
__global__ void __launch_bounds__(256) gemm_reduce_kernel(const float* __restrict__ tpu,
                                                          const int* __restrict__ rf) {
    __shared__ __align__(16) __half Ah[BM*LDK];
    __shared__ __align__(16) __half Bh[BN*LDK];
    __shared__ float pxr[BM], pyr[BM], pxc[BN], pyc[BN];
    __shared__ unsigned long long s_r_all[BM], s_r_un[BM], s_c_all[BN], s_c_un[BN];

    const int b       = blockIdx.z;
    const int rowBase = blockIdx.y * BM;
    const int colBase = blockIdx.x * BN;
    const int tid     = threadIdx.x;
    const int wid     = tid >> 5;
    const int lane    = tid & 31;
    const int gid     = lane >> 2;
    const int tig     = lane & 3;

    float relax = decode_relax(rf);

    const int rowW = (wid & 1) * 64;
    const int colW = (wid >> 1) * 32;

    const size_t baseA = ((size_t)b*NN + rowBase)*CC;
    const size_t baseB = ((size_t)b*NN + colBase)*CC;

    if (tid < 128) {
        const float* px = tpu + (size_t)b*2*NN;
        const float* py = px + NN;
        pxr[tid] = px[rowBase + tid]; pyr[tid] = py[rowBase + tid];
        pxc[tid] = px[colBase + tid]; pyc[tid] = py[colBase + tid];
        s_r_all[tid] = 0ULL; s_r_un[tid] = 0ULL;
        s_c_all[tid] = 0ULL; s_c_un[tid] = 0ULL;
    }

    // load A,B tiles (128 rows x 64 halves each) via uint4
    #pragma unroll
    for (int it = 0; it < 4; it++) {
        int idx = tid + it*256;          // 0..1023
        int row = idx >> 3, seg = idx & 7;
        *(uint4*)(Ah + row*LDK + seg*8) = *(const uint4*)(g_sdh + baseA + (size_t)row*CC + seg*8);
        *(uint4*)(Bh + row*LDK + seg*8) = *(const uint4*)(g_tdh + baseB + (size_t)row*CC + seg*8);
    }
    __syncthreads();

    float acc[4][4][4];
    #pragma unroll
    for (int mt = 0; mt < 4; mt++)
        #pragma unroll
        for (int nt = 0; nt < 4; nt++)
            #pragma unroll
            for (int e = 0; e < 4; e++) acc[mt][nt][e] = 0.f;

    const unsigned Ah_base = (unsigned)__cvta_generic_to_shared(Ah);
    const unsigned aoff = ((lane & 15)*LDK + (lane >> 4)*8) * 2;

    #pragma unroll
    for (int ks = 0; ks < 4; ks++) {
        const int kk = ks*16;
        unsigned bfr[4][2];
        #pragma unroll
        for (int nt = 0; nt < 4; nt++) {
            int col = colW + nt*8 + gid;
            bfr[nt][0] = *(const unsigned*)(Bh + col*LDK + kk + 2*tig);
            bfr[nt][1] = *(const unsigned*)(Bh + col*LDK + kk + 8 + 2*tig);
        }
        #pragma unroll
        for (int mt = 0; mt < 4; mt++) {
            unsigned a0, a1, a2, a3;
            ldmatrix_x4(a0, a1, a2, a3, Ah_base + ((rowW + mt*16)*LDK + kk)*2 + aoff);
            #pragma unroll
            for (int nt = 0; nt < 4; nt++)
                mma_f16(acc[mt][nt], a0, a1, a2, a3, bfr[nt][0], bfr[nt][1]);
        }
    }

    // ---- store D tile (fp16) ----
    #pragma unroll
    for (int mt = 0; mt < 4; mt++) {
        #pragma unroll
        for (int nt = 0; nt < 4; nt++) {
            int r0 = rowW + mt*16 + gid;
            int c0 = colW + nt*8 + tig*2;
            __half2 p0 = __floats2half2_rn(acc[mt][nt][0], acc[mt][nt][1]);
            __half2 p1 = __floats2half2_rn(acc[mt][nt][2], acc[mt][nt][3]);
            size_t rowA = ((size_t)b*NN + rowBase + r0)*NN + colBase + c0;
            *(__half2*)(g_D + rowA) = p0;
            *(__half2*)(g_D + rowA + (size_t)8*NN) = p1;
        }
    }

    // ---- approx row (st) argmax ----
    #pragma unroll
    for (int mt = 0; mt < 4; mt++) {
        #pragma unroll
        for (int half = 0; half < 2; half++) {
            int r_loc = rowW + mt*16 + gid + half*8;
            float prx = pxr[r_loc], pry = pyr[r_loc];
            float va = -3.f, vu = -3.f;
            int   ia = 0,    iu = 0;
            #pragma unroll
            for (int nt = 0; nt < 4; nt++) {
                #pragma unroll
                for (int e = 0; e < 2; e++) {
                    int c_loc = colW + nt*8 + tig*2 + e;
                    float v = acc[mt][nt][half*2 + e];
                    int idx = colBase + c_loc;
                    if (v > va) { va = v; ia = idx; }
                    bool m = (fabsf(pxc[c_loc]-prx) <= relax) && (fabsf(pyc[c_loc]-pry) <= relax);
                    if (!m && v > vu) { vu = v; iu = idx; }
                }
            }
            #pragma unroll
            for (int s = 1; s <= 2; s <<= 1) {
                float ov = __shfl_xor_sync(0xFFFFFFFFu, va, s);
                int   oi = __shfl_xor_sync(0xFFFFFFFFu, ia, s);
                if (ov > va || (ov == va && oi < ia)) { va = ov; ia = oi; }
                float ow = __shfl_xor_sync(0xFFFFFFFFu, vu, s);
                int   oj = __shfl_xor_sync(0xFFFFFFFFu, iu, s);
                if (ow > vu || (ow == vu && oj < iu)) { vu = ow; iu = oj; }
            }
            if (tig == 0) {
                atomicMax(&s_r_all[r_loc], make_key(va, ia));
                if (vu > -2.5f) atomicMax(&s_r_un[r_loc], make_key(vu, iu));
            }
        }
    }
    // ---- approx col (ts) argmax ----
    #pragma unroll
    for (int nt = 0; nt < 4; nt++) {
        #pragma unroll
        for (int e = 0; e < 2; e++) {
            int c_loc = colW + nt*8 + tig*2 + e;
            float pcx = pxc[c_loc], pcy = pyc[c_loc];
            float va = -3.f, vu = -3.f;
            int   ia = 0,    iu = 0;
            #pragma unroll
            for (int mt = 0; mt < 4; mt++) {
                #pragma unroll
                for (int half = 0; half < 2; half++) {
                    int r_loc = rowW + mt*16 + gid + half*8;
                    float v = acc[mt][nt][half*2 + e];
                    int idx = rowBase + r_loc;
                    if (v > va) { va = v; ia = idx; }
                    bool m = (fabsf(pxr[r_loc]-pcx) <= relax) && (fabsf(pyr[r_loc]-pcy) <= relax);
                    if (!m && v > vu) { vu = v; iu = idx; }
                }
            }
            #pragma unroll
            for (int s = 4; s <= 16; s <<= 1) {
                float ov = __shfl_xor_sync(0xFFFFFFFFu, va, s);
                int   oi = __shfl_xor_sync(0xFFFFFFFFu, ia, s);
                if (ov > va || (ov == va && oi < ia)) { va = ov; ia = oi; }
                float ow = __shfl_xor_sync(0xFFFFFFFFu, vu, s);
                int   oj = __shfl_xor_sync(0xFFFFFFFFu, iu, s);
                if (ow > vu || (ow == vu && oj < iu)) { vu = ow; iu = oj; }
            }
            if (gid == 0) {
                atomicMax(&s_c_all[c_loc], make_key(va, ia));
                if (vu > -2.5f) atomicMax(&s_c_un[c_loc], make_key(vu, iu));
            }
        }
    }
    __syncthreads();
    if (tid < 128) {
        atomicMax(&g_row_all[(size_t)b*NN + rowBase + tid], s_r_all[tid]);
        if (s_r_un[tid]) atomicMax(&g_row_un[(size_t)b*NN + rowBase + tid], s_r_un[tid]);
        atomicMax(&g_col_all[(size_t)b*NN + colBase + tid], s_c_all[tid]);
        if (s_c_un[tid]) atomicMax(&g_col_un[(size_t)b*NN + colBase + tid], s_c_un[tid]);
    }
}

// ---------------- 4. exact refinement, row (st) direction: warp per row ----------------
__global__ void refine_row_kernel(const float* __restrict__ tpu, const int* __restrict__ rf) {
    int gw   = (blockIdx.x*blockDim.x + threadIdx.x) >> 5;
    int lane = threadIdx.x & 31;
    int b = gw / NN, i = gw - b*NN;
    float relax = decode_relax(rf);

    const float* px = tpu + (size_t)b*2*NN;
    const float* py = px + NN;
    size_t base = (size_t)b*NN + i;

    unsigned long long kra = g_row_all[base];
    unsigned long long kru = g_row_un [base];
    float gall = key_dot(kra) - THR;
    bool haveUn = (kru != 0ULL);
    float gun = haveUn ? key_dot(kru) - THR : 1e30f;
    float pxa = px[i], pya = py[i];

    const __half2* Drow = (const __half2*)(g_D + base*NN);
    const float* av = g_sd + base*CC;

    unsigned long long ka = 0ULL, ku = 0ULL;
    for (int h = lane; h < NN/2; h += 32) {
        float2 v = __half22float2(Drow[h]);
        #pragma unroll
        for (int e = 0; e < 2; e++) {
            float vv = e ? v.y : v.x;
            int j = 2*h + e;
            bool cA = vv >= gall;
            bool cU = haveUn && vv >= gun;
            if (cA || cU) {
                if (cU) {
                    bool m = (fabsf(px[j]-pxa) <= relax) && (fabsf(py[j]-pya) <= relax);
                    cU = !m;
                }
                if (cA || cU) {
                    float s = exact_dot(av, g_td + ((size_t)b*NN + j)*CC);
                    unsigned long long key = make_key(s, j);
                    if (cA && key > ka) ka = key;
                    if (cU && key > ku) ku = key;
                }
            }
        }
    }
    #pragma unroll
    for (int m = 16; m; m >>= 1) {
        unsigned long long oa = __shfl_xor_sync(0xFFFFFFFFu, ka, m);
        unsigned long long ou = __shfl_xor_sync(0xFFFFFFFFu, ku, m);
        if (oa > ka) ka = oa;
        if (ou > ku) ku = ou;
    }
    if (lane == 0) {
        g_row_all[base] = ka;
        g_row_un[base]  = haveUn ? ku : 0ULL;
    }
}

// ---------------- 5. exact refinement, col (ts) direction: thread per col ----------------
__global__ void refine_col_kernel(const float* __restrict__ tpu, const int* __restrict__ rf) {
    int b = blockIdx.y;
    int j = blockIdx.x*128 + threadIdx.x;
    float relax = decode_relax(rf);

    const float* px = tpu + (size_t)b*2*NN;
    const float* py = px + NN;
    size_t base = (size_t)b*NN + j;

    unsigned long long kca = g_col_all[base];
    unsigned long long kcu = g_col_un [base];
    float gall = key_dot(kca) - THR;
    bool haveUn = (kcu != 0ULL);
    float gun = haveUn ? key_dot(kcu) - THR : 1e30f;
    float pxa = px[j], pya = py[j];

    const __half* Dp = g_D + (size_t)b*NN*NN + j;
    const float* av = g_td + base*CC;

    unsigned long long ka = 0ULL, ku = 0ULL;
    #pragma unroll 4
    for (int r = 0; r < NN; r++) {
        float vv = __half2float(Dp[(size_t)r*NN]);
        bool cA = vv >= gall;
        bool cU = haveUn && vv >= gun;
        if (cA || cU) {
            if (cU) {
                bool m = (fabsf(px[r]-pxa) <= relax) && (fabsf(py[r]-pya) <= relax);
                cU = !m;
            }
            if (cA || cU) {
                float s = exact_dot(av, g_sd + ((size_t)b*NN + r)*CC);
                unsigned long long key = make_key(s, r);
                if (cA && key > ka) ka = key;
                if (cU && key > ku) ku = key;
            }
        }
    }
    g_col_all[base] = ka;
    g_col_un[base]  = haveUn ? ku : 0ULL;
}

// ---------------- 6. triplet loss + recall ----------------
__global__ void finalize_kernel(const float* __restrict__ tpu) {
    __shared__ float s_loss[8], s_corr[8];
    int gw   = (blockIdx.x*blockDim.x + threadIdx.x) >> 5;
    int lane = threadIdx.x & 31;
    int warp = threadIdx.x >> 5;

    int b = gw / NN;
    int i = gw - b*NN;
    const float* px = tpu + (size_t)b*2*NN;
    const float* py = px + NN;
    size_t base = (size_t)b*NN + i;

    unsigned long long kra = g_row_all[base];
    unsigned long long kru = g_row_un [base];
    unsigned long long kca = g_col_all[base];
    unsigned long long kcu = g_col_un [base];

    int nn_st = key_idx(kra);
    int nn_ts = key_idx(kca);
    int neg_st, neg_ts;
    float d_st, d_ts;
    if (kru == 0ULL) { neg_st = 0; d_st = 2.f; }
    else { neg_st = key_idx(kru); d_st = dist_from_dot(key_dot(kru)); }
    if (kcu == 0ULL) { neg_ts = 0; d_ts = 2.f; }
    else { neg_ts = key_idx(kcu); d_ts = dist_from_dot(key_dot(kcu)); }

    bool take_ts = d_ts < d_st;
    const float* a = (take_ts ? g_td : g_sd) + base*CC;
    const float* p = (take_ts ? g_sd : g_td) + base*CC;
    const float* n = take_ts ? (g_sd + ((size_t)b*NN + neg_ts)*CC)
                             : (g_td + ((size_t)b*NN + neg_st)*CC);

    float dp2 = 0.f, dn2 = 0.f;
    #pragma unroll
    for (int c = lane; c < CC; c += 32) {
        float av = a[c];
        float e1 = av - p[c] + 1e-6f; dp2 = fmaf(e1, e1, dp2);
        float e2 = av - n[c] + 1e-6f; dn2 = fmaf(e2, e2, dn2);
    }
    #pragma unroll
    for (int m = 16; m; m >>= 1) {
        dp2 += __shfl_xor_sync(0xFFFFFFFFu, dp2, m);
        dn2 += __shfl_xor_sync(0xFFFFFFFFu, dn2, m);
    }
    if (lane == 0) {
        float loss = fmaxf(sqrtf(dp2) - sqrtf(dn2) + 0.2f, 0.f);
        float corr = 0.f;
        float pxi = px[i], pyi = py[i];
        if (px[nn_st] == pxi && py[nn_st] == pyi) corr += 1.f;
        if (px[nn_ts] == pxi && py[nn_ts] == pyi) corr += 1.f;
        s_loss[warp] = loss;
        s_corr[warp] = corr;
    }
    __syncthreads();
    if (threadIdx.x == 0) {
        float L = 0.f, Cr = 0.f;
        #pragma unroll
        for (int w = 0; w < 8; w++) { L += s_loss[w]; Cr += s_corr[w]; }
        atomicAdd(&g_acc[0], L);
        atomicAdd(&g_acc[1], Cr);
    }
}

// ---------------- 7. write outputs ----------------
__global__ void writeout_kernel(float* __restrict__ out) {
    out[0] = g_acc[0] / (float)(BB*NN);
    out[1] = g_acc[1] / (float)(2*BB*NN);
}

// ---------------- launch ----------------
extern "C" void kernel_launch(void* const* d_in, const int* in_sizes, int n_in,
                              void* d_out, int out_size) {
    const float* src = (const float*)d_in[0];
    const float* tgt = (const float*)d_in[1];
    const float* spn = (const float*)d_in[2];
    const float* tpn = (const float*)d_in[3];
    const float* tpu = (const float*)d_in[4];
    const int*   rf  = (const int*)  d_in[5];
    float* out = (float*)d_out;

    dim3 tgrid(NN/32, CC/32, BB*2);
    transpose_kernel<<<tgrid, 256>>>(src, tgt);
    sample_kernel<<<(BB*2*NN)/8, 256>>>(spn, tpn);

    dim3 grid(NTILE, NTILE, BB);
    gemm_reduce_kernel<<<grid, 256>>>(tpu, rf);

    refine_row_kernel<<<(BB*NN)/8, 256>>>(tpu, rf);
    dim3 cgrid(NN/128, BB);
    refine_col_kernel<<<cgrid, 128>>>(tpu, rf);

    finalize_kernel<<<(BB*NN)/8, 256>>>(tpu);
    writeout_kernel<<<1, 1>>>(out);
}

// round 8
// speedup vs baseline: 6.5219x; 6.5219x over previous
#include <cuda_runtime.h>
#include <cuda_fp16.h>
#include <cstdint>

#define BB 4
#define CC 64
#define HH 48
#define WW 64
#define NN (HH*WW)        // 3072
#define BM 128
#define BN 128
#define NTILE (NN/BM)     // 24
#define LDK 72            // smem row stride in halves (144B): ldmatrix-aligned, conflict-free

// ---------------- device scratch ----------------
__device__ float g_srcT[BB*NN*CC];
__device__ float g_tgtT[BB*NN*CC];
__device__ float g_sd[BB*NN*CC];     // f32 descriptors (finalize)
__device__ float g_td[BB*NN*CC];
__device__ __half g_sdh[BB*NN*CC];   // fp16 split hi
__device__ __half g_sdl[BB*NN*CC];   // fp16 split lo
__device__ __half g_tdh[BB*NN*CC];
__device__ __half g_tdl[BB*NN*CC];
__device__ unsigned long long g_row_all[BB*NN];
__device__ unsigned long long g_row_un [BB*NN];
__device__ unsigned long long g_col_all[BB*NN];
__device__ unsigned long long g_col_un [BB*NN];
__device__ float g_acc[2];

// ---------------- key packing ----------------
__device__ __forceinline__ unsigned long long make_key(float f, int idx) {
    unsigned u = __float_as_uint(f);
    u = (u & 0x80000000u) ? ~u : (u | 0x80000000u);
    return ((unsigned long long)u << 32) | (unsigned)(0xFFFFFFFFu - (unsigned)idx);
}
__device__ __forceinline__ float key_dot(unsigned long long k) {
    unsigned u = (unsigned)(k >> 32);
    return (u & 0x80000000u) ? __uint_as_float(u ^ 0x80000000u) : __uint_as_float(~u);
}
__device__ __forceinline__ int key_idx(unsigned long long k) {
    return (int)(0xFFFFFFFFu - (unsigned)(k & 0xFFFFFFFFu));
}
__device__ __forceinline__ float dist_from_dot(float d) {
    d = fminf(fmaxf(d, -1.f), 1.f);
    return sqrtf(fmaxf(2.f - 2.f*d, 0.f));
}
__device__ __forceinline__ void ldmatrix_x4(unsigned& r0, unsigned& r1, unsigned& r2,
                                            unsigned& r3, unsigned addr) {
    asm volatile("ldmatrix.sync.aligned.m8n8.x4.shared.b16 {%0,%1,%2,%3}, [%4];"
        : "=r"(r0), "=r"(r1), "=r"(r2), "=r"(r3) : "r"(addr));
}
__device__ __forceinline__ void mma_f16(float* c, unsigned a0, unsigned a1,
                                        unsigned a2, unsigned a3,
                                        unsigned b0, unsigned b1) {
    asm volatile(
        "mma.sync.aligned.m16n8k16.row.col.f32.f16.f16.f32 "
        "{%0,%1,%2,%3}, {%4,%5,%6,%7}, {%8,%9}, {%0,%1,%2,%3};\n"
        : "+f"(c[0]), "+f"(c[1]), "+f"(c[2]), "+f"(c[3])
        : "r"(a0), "r"(a1), "r"(a2), "r"(a3), "r"(b0), "r"(b1));
}

// ---------------- 1. coalesced transpose + init ----------------
__global__ void transpose_kernel(const float* __restrict__ src, const float* __restrict__ tgt) {
    __shared__ float tile[32][33];
    int arr = blockIdx.z >> 2, b = blockIdx.z & 3;
    const float* in = arr ? tgt : src;
    float* out = arr ? g_tgtT : g_srcT;
    int p0 = blockIdx.x*32, c0 = blockIdx.y*32;
    int tx = threadIdx.x & 31, ty = threadIdx.x >> 5;
    #pragma unroll
    for (int q = 0; q < 4; q++)
        tile[ty + q*8][tx] = in[((size_t)b*CC + c0 + ty + q*8)*NN + p0 + tx];
    __syncthreads();
    #pragma unroll
    for (int q = 0; q < 4; q++)
        out[((size_t)b*NN + p0 + ty + q*8)*CC + c0 + tx] = tile[tx][ty + q*8];
    int gi = ((blockIdx.z*gridDim.y + blockIdx.y)*gridDim.x + blockIdx.x)*256 + threadIdx.x;
    if (gi < BB*NN) {
        g_row_all[gi] = 0ULL; g_row_un[gi] = 0ULL;
        g_col_all[gi] = 0ULL; g_col_un[gi] = 0ULL;
    }
    if (gi < 2) g_acc[gi] = 0.f;
}

// ---------------- 2. bilinear sample + normalize + fp16 hi/lo split ----------------
__global__ void sample_kernel(const float* __restrict__ spn, const float* __restrict__ tpn) {
    int gw   = (blockIdx.x*blockDim.x + threadIdx.x) >> 5;
    int lane = threadIdx.x & 31;
    int b    = gw / (2*NN);
    int rem  = gw - b*2*NN;
    int side = rem / NN;
    int p    = rem - side*NN;

    const float* g = (side ? tpn : spn) + ((size_t)b*NN + p)*2;
    float gx = g[0], gy = g[1];
    const float* img = (side ? g_tgtT : g_srcT) + (size_t)b*NN*CC;

    float x = ((gx + 1.f)*WW - 1.f)*0.5f;
    float y = ((gy + 1.f)*HH - 1.f)*0.5f;
    float x0f = floorf(x), y0f = floorf(y);
    int x0 = (int)x0f, y0 = (int)y0f;
    int x1 = x0 + 1,   y1 = y0 + 1;
    float wx1 = x - x0f, wx0 = 1.f - wx1;
    float wy1 = y - y0f, wy0 = 1.f - wy1;

    float v0 = 0.f, v1 = 0.f;
    #define CORNER(XI, YI, WGT) do { \
        if ((XI) >= 0 && (XI) < WW && (YI) >= 0 && (YI) < HH) { \
            const float* q = img + ((size_t)(YI)*WW + (XI))*CC; \
            v0 += (WGT)*q[lane]; v1 += (WGT)*q[lane+32]; \
        } } while(0)
    CORNER(x0, y0, wx0*wy0);
    CORNER(x1, y0, wx1*wy0);
    CORNER(x0, y1, wx0*wy1);
    CORNER(x1, y1, wx1*wy1);
    #undef CORNER

    float ss = v0*v0 + v1*v1;
    #pragma unroll
    for (int m = 16; m; m >>= 1) ss += __shfl_xor_sync(0xFFFFFFFFu, ss, m);
    float inv = 1.f / fmaxf(sqrtf(ss), 1e-12f);

    size_t base = ((size_t)b*NN + p)*CC;
    float*  outf = (side ? g_td  : g_sd ) + base;
    __half* outh = (side ? g_tdh : g_sdh) + base;
    __half* outl = (side ? g_tdl : g_sdl) + base;
    float s0 = v0*inv, s1 = v1*inv;
    outf[lane]    = s0;
    outf[lane+32] = s1;
    __half h0 = __float2half_rn(s0);
    __half h1 = __float2half_rn(s1);
    outh[lane]    = h0;
    outh[lane+32] = h1;
    outl[lane]    = __float2half_rn(s0 - __half2float(h0));
    outl[lane+32] = __float2half_rn(s1 - __half2float(h1));
}

// ---------------- dummy: shifts gemm to profiled launch index 3 ----------------
__global__ void dummy_kernel() {}

// ---------------- 3. fp16x3 tensor GEMM + fused argmax (single K phase) ----------------
__global__ void __launch_bounds__(256) gemm_reduce_kernel(const float* __restrict__ tpu,
                                                          const int* __restrict__ rf) {
    extern __shared__ __align__(16) __half smh[];
    __half* Ah = smh;                 // 128 x LDK
    __half* Al = Ah + BM*LDK;
    __half* Bh = Al + BM*LDK;
    __half* Bl = Bh + BN*LDK;

    __shared__ float pxr[BM], pyr[BM], pxc[BN], pyc[BN];
    __shared__ unsigned long long s_r_all[BM], s_r_un[BM], s_c_all[BN], s_c_un[BN];

    const int b       = blockIdx.z;
    const int rowBase = blockIdx.y * BM;
    const int colBase = blockIdx.x * BN;
    const int tid     = threadIdx.x;
    const int wid     = tid >> 5;
    const int lane    = tid & 31;
    const int gid     = lane >> 2;
    const int tig     = lane & 3;

    int rv = rf[0];
    float relax = (rv >= 0 && rv < 1000000) ? (float)rv : __int_as_float(rv);

    const int rowW = (wid & 1) * 64;
    const int colW = (wid >> 1) * 32;

    const size_t baseA = ((size_t)b*NN + rowBase)*CC;
    const size_t baseB = ((size_t)b*NN + colBase)*CC;

    if (tid < 128) {
        const float* px = tpu + (size_t)b*2*NN;
        const float* py = px + NN;
        pxr[tid] = px[rowBase + tid]; pyr[tid] = py[rowBase + tid];
        pxc[tid] = px[colBase + tid]; pyc[tid] = py[colBase + tid];
        s_r_all[tid] = 0ULL; s_r_un[tid] = 0ULL;
        s_c_all[tid] = 0ULL; s_c_un[tid] = 0ULL;
    }

    // single-phase load: 4 tiles x 128 rows x 8 x 16B = 4096 uint4
    #pragma unroll
    for (int it = 0; it < 16; it++) {
        const int arr = it >> 2;                 // compile-time
        const int idx = tid + (it & 3)*256;      // 0..1023
        const int row = idx >> 3, seg = idx & 7;
        const __half* gsrc = (arr == 0) ? (g_sdh + baseA) :
                             (arr == 1) ? (g_sdl + baseA) :
                             (arr == 2) ? (g_tdh + baseB) : (g_tdl + baseB);
        __half* sdst = (arr == 0) ? Ah : (arr == 1) ? Al : (arr == 2) ? Bh : Bl;
        *(uint4*)(sdst + row*LDK + seg*8) = *(const uint4*)(gsrc + (size_t)row*CC + seg*8);
    }
    __syncthreads();

    float acc[4][4][4];
    #pragma unroll
    for (int mt = 0; mt < 4; mt++)
        #pragma unroll
        for (int nt = 0; nt < 4; nt++)
            #pragma unroll
            for (int e = 0; e < 4; e++) acc[mt][nt][e] = 0.f;

    const unsigned Ah_base = (unsigned)__cvta_generic_to_shared(Ah);
    const unsigned Al_base = (unsigned)__cvta_generic_to_shared(Al);
    const unsigned aoff = ((lane & 15)*LDK + (lane >> 4)*8) * 2;

    #pragma unroll
    for (int ks = 0; ks < 4; ks++) {
        const int kk = ks*16;
        unsigned bh[4][2], bl[4][2];
        #pragma unroll
        for (int nt = 0; nt < 4; nt++) {
            int col = colW + nt*8 + gid;
            bh[nt][0] = *(const unsigned*)(Bh + col*LDK + kk + 2*tig);
            bh[nt][1] = *(const unsigned*)(Bh + col*LDK + kk + 8 + 2*tig);
            bl[nt][0] = *(const unsigned*)(Bl + col*LDK + kk + 2*tig);
            bl[nt][1] = *(const unsigned*)(Bl + col*LDK + kk + 8 + 2*tig);
        }
        #pragma unroll
        for (int mt = 0; mt < 4; mt++) {
            const unsigned tileoff = ((rowW + mt*16)*LDK + kk)*2;
            unsigned ah0, ah1, ah2, ah3, al0, al1, al2, al3;
            ldmatrix_x4(ah0, ah1, ah2, ah3, Ah_base + tileoff + aoff);
            ldmatrix_x4(al0, al1, al2, al3, Al_base + tileoff + aoff);
            #pragma unroll
            for (int nt = 0; nt < 4; nt++) {
                mma_f16(acc[mt][nt], ah0, ah1, ah2, ah3, bh[nt][0], bh[nt][1]);
                mma_f16(acc[mt][nt], ah0, ah1, ah2, ah3, bl[nt][0], bl[nt][1]);
                mma_f16(acc[mt][nt], al0, al1, al2, al3, bh[nt][0], bh[nt][1]);
            }
        }
    }

    // ---- row (st) argmax ----
    #pragma unroll
    for (int mt = 0; mt < 4; mt++) {
        #pragma unroll
        for (int half = 0; half < 2; half++) {
            int r_loc = rowW + mt*16 + gid + half*8;
            float prx = pxr[r_loc], pry = pyr[r_loc];
            float va = -3.f, vu = -3.f;
            int   ia = 0,    iu = 0;
            #pragma unroll
            for (int nt = 0; nt < 4; nt++) {
                #pragma unroll
                for (int e = 0; e < 2; e++) {
                    int c_loc = colW + nt*8 + tig*2 + e;
                    float v = acc[mt][nt][half*2 + e];
                    int idx = colBase + c_loc;
                    if (v > va) { va = v; ia = idx; }
                    bool m = (fabsf(pxc[c_loc]-prx) <= relax) && (fabsf(pyc[c_loc]-pry) <= relax);
                    if (!m && v > vu) { vu = v; iu = idx; }
                }
            }
            #pragma unroll
            for (int s = 1; s <= 2; s <<= 1) {
                float ov = __shfl_xor_sync(0xFFFFFFFFu, va, s);
                int   oi = __shfl_xor_sync(0xFFFFFFFFu, ia, s);
                if (ov > va || (ov == va && oi < ia)) { va = ov; ia = oi; }
                float ow = __shfl_xor_sync(0xFFFFFFFFu, vu, s);
                int   oj = __shfl_xor_sync(0xFFFFFFFFu, iu, s);
                if (ow > vu || (ow == vu && oj < iu)) { vu = ow; iu = oj; }
            }
            if (tig == 0) {
                atomicMax(&s_r_all[r_loc], make_key(va, ia));
                if (vu > -2.5f) atomicMax(&s_r_un[r_loc], make_key(vu, iu));
            }
        }
    }
    // ---- col (ts) argmax ----
    #pragma unroll
    for (int nt = 0; nt < 4; nt++) {
        #pragma unroll
        for (int e = 0; e < 2; e++) {
            int c_loc = colW + nt*8 + tig*2 + e;
            float pcx = pxc[c_loc], pcy = pyc[c_loc];
            float va = -3.f, vu = -3.f;
            int   ia = 0,    iu = 0;
            #pragma unroll
            for (int mt = 0; mt < 4; mt++) {
                #pragma unroll
                for (int half = 0; half < 2; half++) {
                    int r_loc = rowW + mt*16 + gid + half*8;
                    float v = acc[mt][nt][half*2 + e];
                    int idx = rowBase + r_loc;
                    if (v > va) { va = v; ia = idx; }
                    bool m = (fabsf(pxr[r_loc]-pcx) <= relax) && (fabsf(pyr[r_loc]-pcy) <= relax);
                    if (!m && v > vu) { vu = v; iu = idx; }
                }
            }
            #pragma unroll
            for (int s = 4; s <= 16; s <<= 1) {
                float ov = __shfl_xor_sync(0xFFFFFFFFu, va, s);
                int   oi = __shfl_xor_sync(0xFFFFFFFFu, ia, s);
                if (ov > va || (ov == va && oi < ia)) { va = ov; ia = oi; }
                float ow = __shfl_xor_sync(0xFFFFFFFFu, vu, s);
                int   oj = __shfl_xor_sync(0xFFFFFFFFu, iu, s);
                if (ow > vu || (ow == vu && oj < iu)) { vu = ow; iu = oj; }
            }
            if (gid == 0) {
                atomicMax(&s_c_all[c_loc], make_key(va, ia));
                if (vu > -2.5f) atomicMax(&s_c_un[c_loc], make_key(vu, iu));
            }
        }
    }
    __syncthreads();
    if (tid < 128) {
        atomicMax(&g_row_all[(size_t)b*NN + rowBase + tid], s_r_all[tid]);
        if (s_r_un[tid]) atomicMax(&g_row_un[(size_t)b*NN + rowBase + tid], s_r_un[tid]);
        atomicMax(&g_col_all[(size_t)b*NN + colBase + tid], s_c_all[tid]);
        if (s_c_un[tid]) atomicMax(&g_col_un[(size_t)b*NN + colBase + tid], s_c_un[tid]);
    }
}

// ---------------- 4. triplet loss + recall ----------------
__global__ void finalize_kernel(const float* __restrict__ tpu) {
    __shared__ float s_loss[8], s_corr[8];
    int gw   = (blockIdx.x*blockDim.x + threadIdx.x) >> 5;
    int lane = threadIdx.x & 31;
    int warp = threadIdx.x >> 5;

    int b = gw / NN;
    int i = gw - b*NN;
    const float* px = tpu + (size_t)b*2*NN;
    const float* py = px + NN;
    size_t base = (size_t)b*NN + i;

    unsigned long long kra = g_row_all[base];
    unsigned long long kru = g_row_un [base];
    unsigned long long kca = g_col_all[base];
    unsigned long long kcu = g_col_un [base];

    int nn_st = key_idx(kra);
    int nn_ts = key_idx(kca);
    int neg_st, neg_ts;
    float d_st, d_ts;
    if (kru == 0ULL) { neg_st = 0; d_st = 2.f; }
    else { neg_st = key_idx(kru); d_st = dist_from_dot(key_dot(kru)); }
    if (kcu == 0ULL) { neg_ts = 0; d_ts = 2.f; }
    else { neg_ts = key_idx(kcu); d_ts = dist_from_dot(key_dot(kcu)); }

    bool take_ts = d_ts < d_st;
    const float* a = (take_ts ? g_td : g_sd) + base*CC;
    const float* p = (take_ts ? g_sd : g_td) + base*CC;
    const float* n = take_ts ? (g_sd + ((size_t)b*NN + neg_ts)*CC)
                             : (g_td + ((size_t)b*NN + neg_st)*CC);

    float dp2 = 0.f, dn2 = 0.f;
    #pragma unroll
    for (int c = lane; c < CC; c += 32) {
        float av = a[c];
        float e1 = av - p[c] + 1e-6f; dp2 = fmaf(e1, e1, dp2);
        float e2 = av - n[c] + 1e-6f; dn2 = fmaf(e2, e2, dn2);
    }
    #pragma unroll
    for (int m = 16; m; m >>= 1) {
        dp2 += __shfl_xor_sync(0xFFFFFFFFu, dp2, m);
        dn2 += __shfl_xor_sync(0xFFFFFFFFu, dn2, m);
    }
    if (lane == 0) {
        float loss = fmaxf(sqrtf(dp2) - sqrtf(dn2) + 0.2f, 0.f);
        float corr = 0.f;
        float pxi = px[i], pyi = py[i];
        if (px[nn_st] == pxi && py[nn_st] == pyi) corr += 1.f;
        if (px[nn_ts] == pxi && py[nn_ts] == pyi) corr += 1.f;
        s_loss[warp] = loss;
        s_corr[warp] = corr;
    }
    __syncthreads();
    if (threadIdx.x == 0) {
        float L = 0.f, Cr = 0.f;
        #pragma unroll
        for (int w = 0; w < 8; w++) { L += s_loss[w]; Cr += s_corr[w]; }
        atomicAdd(&g_acc[0], L);
        atomicAdd(&g_acc[1], Cr);
    }
}

// ---------------- 5. write outputs ----------------
__global__ void writeout_kernel(float* __restrict__ out) {
    out[0] = g_acc[0] / (float)(BB*NN);
    out[1] = g_acc[1] / (float)(2*BB*NN);
}

// ---------------- launch ----------------
extern "C" void kernel_launch(void* const* d_in, const int* in_sizes, int n_in,
                              void* d_out, int out_size) {
    const float* src = (const float*)d_in[0];
    const float* tgt = (const float*)d_in[1];
    const float* spn = (const float*)d_in[2];
    const float* tpn = (const float*)d_in[3];
    const float* tpu = (const float*)d_in[4];
    const int*   rf  = (const int*)  d_in[5];
    float* out = (float*)d_out;

    const int DSMEM = 4*BM*LDK*sizeof(__half);   // 73728 B
    cudaFuncSetAttribute(gemm_reduce_kernel,
                         cudaFuncAttributeMaxDynamicSharedMemorySize, DSMEM);

    dim3 tgrid(NN/32, CC/32, BB*2);
    transpose_kernel<<<tgrid, 256>>>(src, tgt);          // launch 0
    sample_kernel<<<(BB*2*NN)/8, 256>>>(spn, tpn);       // launch 1
    dummy_kernel<<<1, 32>>>();                           // launch 2 (profiling shim)

    dim3 grid(NTILE, NTILE, BB);
    gemm_reduce_kernel<<<grid, 256, DSMEM>>>(tpu, rf);   // launch 3 -> ncu target

    finalize_kernel<<<(BB*NN)/8, 256>>>(tpu);            // launch 4
    writeout_kernel<<<1, 1>>>(out);                      // launch 5
}

// round 9
// speedup vs baseline: 8.9811x; 1.3771x over previous
#include <cuda_runtime.h>
#include <cuda_fp16.h>
#include <cstdint>

#define BB 4
#define CC 64
#define HH 48
#define WW 64
#define NN (HH*WW)        // 3072
#define BM 128
#define BN 128
#define NTILE (NN/BM)     // 24
#define KC 32             // K chunk (halves)
#define LDK 40            // smem row stride in halves (80B): ldmatrix + LDS conflict-free

// ---------------- device scratch ----------------
__device__ float g_srcT[BB*NN*CC];
__device__ float g_tgtT[BB*NN*CC];
__device__ float g_sd[BB*NN*CC];     // f32 descriptors (finalize)
__device__ float g_td[BB*NN*CC];
__device__ __half g_sdh[BB*NN*CC];   // fp16 split hi
__device__ __half g_sdl[BB*NN*CC];   // fp16 split lo
__device__ __half g_tdh[BB*NN*CC];
__device__ __half g_tdl[BB*NN*CC];
__device__ unsigned long long g_row_all[BB*NN];
__device__ unsigned long long g_row_un [BB*NN];
__device__ unsigned long long g_col_all[BB*NN];
__device__ unsigned long long g_col_un [BB*NN];
__device__ float g_acc[2];

// ---------------- key packing ----------------
__device__ __forceinline__ unsigned long long make_key(float f, int idx) {
    unsigned u = __float_as_uint(f);
    u = (u & 0x80000000u) ? ~u : (u | 0x80000000u);
    return ((unsigned long long)u << 32) | (unsigned)(0xFFFFFFFFu - (unsigned)idx);
}
__device__ __forceinline__ float key_dot(unsigned long long k) {
    unsigned u = (unsigned)(k >> 32);
    return (u & 0x80000000u) ? __uint_as_float(u ^ 0x80000000u) : __uint_as_float(~u);
}
__device__ __forceinline__ int key_idx(unsigned long long k) {
    return (int)(0xFFFFFFFFu - (unsigned)(k & 0xFFFFFFFFu));
}
__device__ __forceinline__ float dist_from_dot(float d) {
    d = fminf(fmaxf(d, -1.f), 1.f);
    return sqrtf(fmaxf(2.f - 2.f*d, 0.f));
}
__device__ __forceinline__ void ldmatrix_x4(unsigned& r0, unsigned& r1, unsigned& r2,
                                            unsigned& r3, unsigned addr) {
    asm volatile("ldmatrix.sync.aligned.m8n8.x4.shared.b16 {%0,%1,%2,%3}, [%4];"
        : "=r"(r0), "=r"(r1), "=r"(r2), "=r"(r3) : "r"(addr));
}
__device__ __forceinline__ void mma_f16(float* c, unsigned a0, unsigned a1,
                                        unsigned a2, unsigned a3,
                                        unsigned b0, unsigned b1) {
    asm volatile(
        "mma.sync.aligned.m16n8k16.row.col.f32.f16.f16.f32 "
        "{%0,%1,%2,%3}, {%4,%5,%6,%7}, {%8,%9}, {%0,%1,%2,%3};\n"
        : "+f"(c[0]), "+f"(c[1]), "+f"(c[2]), "+f"(c[3])
        : "r"(a0), "r"(a1), "r"(a2), "r"(a3), "r"(b0), "r"(b1));
}

// ---------------- 1. coalesced transpose + init ----------------
__global__ void transpose_kernel(const float* __restrict__ src, const float* __restrict__ tgt) {
    __shared__ float tile[32][33];
    int arr = blockIdx.z >> 2, b = blockIdx.z & 3;
    const float* in = arr ? tgt : src;
    float* out = arr ? g_tgtT : g_srcT;
    int p0 = blockIdx.x*32, c0 = blockIdx.y*32;
    int tx = threadIdx.x & 31, ty = threadIdx.x >> 5;
    #pragma unroll
    for (int q = 0; q < 4; q++)
        tile[ty + q*8][tx] = in[((size_t)b*CC + c0 + ty + q*8)*NN + p0 + tx];
    __syncthreads();
    #pragma unroll
    for (int q = 0; q < 4; q++)
        out[((size_t)b*NN + p0 + ty + q*8)*CC + c0 + tx] = tile[tx][ty + q*8];
    int gi = ((blockIdx.z*gridDim.y + blockIdx.y)*gridDim.x + blockIdx.x)*256 + threadIdx.x;
    if (gi < BB*NN) {
        g_row_all[gi] = 0ULL; g_row_un[gi] = 0ULL;
        g_col_all[gi] = 0ULL; g_col_un[gi] = 0ULL;
    }
    if (gi < 2) g_acc[gi] = 0.f;
}

// ---------------- 2. bilinear sample + normalize + fp16 hi/lo split ----------------
__global__ void sample_kernel(const float* __restrict__ spn, const float* __restrict__ tpn) {
    int gw   = (blockIdx.x*blockDim.x + threadIdx.x) >> 5;
    int lane = threadIdx.x & 31;
    int b    = gw / (2*NN);
    int rem  = gw - b*2*NN;
    int side = rem / NN;
    int p    = rem - side*NN;

    const float* g = (side ? tpn : spn) + ((size_t)b*NN + p)*2;
    float gx = g[0], gy = g[1];
    const float* img = (side ? g_tgtT : g_srcT) + (size_t)b*NN*CC;

    float x = ((gx + 1.f)*WW - 1.f)*0.5f;
    float y = ((gy + 1.f)*HH - 1.f)*0.5f;
    float x0f = floorf(x), y0f = floorf(y);
    int x0 = (int)x0f, y0 = (int)y0f;
    int x1 = x0 + 1,   y1 = y0 + 1;
    float wx1 = x - x0f, wx0 = 1.f - wx1;
    float wy1 = y - y0f, wy0 = 1.f - wy1;

    float v0 = 0.f, v1 = 0.f;
    #define CORNER(XI, YI, WGT) do { \
        if ((XI) >= 0 && (XI) < WW && (YI) >= 0 && (YI) < HH) { \
            const float* q = img + ((size_t)(YI)*WW + (XI))*CC; \
            v0 += (WGT)*q[lane]; v1 += (WGT)*q[lane+32]; \
        } } while(0)
    CORNER(x0, y0, wx0*wy0);
    CORNER(x1, y0, wx1*wy0);
    CORNER(x0, y1, wx0*wy1);
    CORNER(x1, y1, wx1*wy1);
    #undef CORNER

    float ss = v0*v0 + v1*v1;
    #pragma unroll
    for (int m = 16; m; m >>= 1) ss += __shfl_xor_sync(0xFFFFFFFFu, ss, m);
    float inv = 1.f / fmaxf(sqrtf(ss), 1e-12f);

    size_t base = ((size_t)b*NN + p)*CC;
    float*  outf = (side ? g_td  : g_sd ) + base;
    __half* outh = (side ? g_tdh : g_sdh) + base;
    __half* outl = (side ? g_tdl : g_sdl) + base;
    float s0 = v0*inv, s1 = v1*inv;
    outf[lane]    = s0;
    outf[lane+32] = s1;
    __half h0 = __float2half_rn(s0);
    __half h1 = __float2half_rn(s1);
    outh[lane]    = h0;
    outh[lane+32] = h1;
    outl[lane]    = __float2half_rn(s0 - __half2float(h0));
    outl[lane+32] = __float2half_rn(s1 - __half2float(h1));
}

// ---------------- dummy: keeps gemm at profiled launch index 3 ----------------
__global__ void dummy_kernel() {}

// ---------------- 3. fp16x3 tensor GEMM, 2-phase K, reordered MMA, fused argmax ----------------
__global__ void __launch_bounds__(256, 2) gemm_reduce_kernel(const float* __restrict__ tpu,
                                                             const int* __restrict__ rf) {
    __shared__ __align__(16) __half Ah[BM*LDK];
    __shared__ __align__(16) __half Al[BM*LDK];
    __shared__ __align__(16) __half Bh[BN*LDK];
    __shared__ __align__(16) __half Bl[BN*LDK];
    __shared__ float pxr[BM], pyr[BM], pxc[BN], pyc[BN];
    __shared__ unsigned long long s_r_all[BM], s_r_un[BM], s_c_all[BN], s_c_un[BN];

    const int b       = blockIdx.z;
    const int rowBase = blockIdx.y * BM;
    const int colBase = blockIdx.x * BN;
    const int tid     = threadIdx.x;
    const int wid     = tid >> 5;
    const int lane    = tid & 31;
    const int gid     = lane >> 2;
    const int tig     = lane & 3;

    int rv = rf[0];
    float relax = (rv >= 0 && rv < 1000000) ? (float)rv : __int_as_float(rv);

    const int rowW = (wid & 1) * 64;
    const int colW = (wid >> 1) * 32;

    const size_t baseA = ((size_t)b*NN + rowBase)*CC;
    const size_t baseB = ((size_t)b*NN + colBase)*CC;

    if (tid < 128) {
        const float* px = tpu + (size_t)b*2*NN;
        const float* py = px + NN;
        pxr[tid] = px[rowBase + tid]; pyr[tid] = py[rowBase + tid];
        pxc[tid] = px[colBase + tid]; pyc[tid] = py[colBase + tid];
        s_r_all[tid] = 0ULL; s_r_un[tid] = 0ULL;
        s_c_all[tid] = 0ULL; s_c_un[tid] = 0ULL;
    }

    float acc[4][4][4];
    #pragma unroll
    for (int mt = 0; mt < 4; mt++)
        #pragma unroll
        for (int nt = 0; nt < 4; nt++)
            #pragma unroll
            for (int e = 0; e < 4; e++) acc[mt][nt][e] = 0.f;

    const unsigned Ah_base = (unsigned)__cvta_generic_to_shared(Ah);
    const unsigned Al_base = (unsigned)__cvta_generic_to_shared(Al);
    const unsigned aoff = ((lane & 15)*LDK + (lane >> 4)*8) * 2;

    #pragma unroll
    for (int kc = 0; kc < 2; kc++) {
        __syncthreads();
        // 4 tiles x 128 rows x 32 halves (4 uint4/row): 2048 uint4 / 256 threads
        #pragma unroll
        for (int it = 0; it < 8; it++) {
            const int arr = it >> 1;                // compile-time
            const int idx = tid + (it & 1)*256;     // 0..511
            const int row = idx >> 2, seg = idx & 3;
            const __half* gsrc = (arr == 0) ? (g_sdh + baseA) :
                                 (arr == 1) ? (g_sdl + baseA) :
                                 (arr == 2) ? (g_tdh + baseB) : (g_tdl + baseB);
            __half* sdst = (arr == 0) ? Ah : (arr == 1) ? Al : (arr == 2) ? Bh : Bl;
            *(uint4*)(sdst + row*LDK + seg*8) =
                *(const uint4*)(gsrc + (size_t)row*CC + kc*KC + seg*8);
        }
        __syncthreads();

        #pragma unroll
        for (int ks = 0; ks < 2; ks++) {
            const int kk = ks*16;
            unsigned bh[4][2], bl[4][2];
            #pragma unroll
            for (int nt = 0; nt < 4; nt++) {
                int col = colW + nt*8 + gid;
                bh[nt][0] = *(const unsigned*)(Bh + col*LDK + kk + 2*tig);
                bh[nt][1] = *(const unsigned*)(Bh + col*LDK + kk + 8 + 2*tig);
                bl[nt][0] = *(const unsigned*)(Bl + col*LDK + kk + 2*tig);
                bl[nt][1] = *(const unsigned*)(Bl + col*LDK + kk + 8 + 2*tig);
            }
            #pragma unroll
            for (int mt = 0; mt < 4; mt++) {
                const unsigned tileoff = ((rowW + mt*16)*LDK + kk)*2;
                unsigned ah0, ah1, ah2, ah3, al0, al1, al2, al3;
                ldmatrix_x4(ah0, ah1, ah2, ah3, Ah_base + tileoff + aoff);
                ldmatrix_x4(al0, al1, al2, al3, Al_base + tileoff + aoff);
                // kind-major: same-acc revisit gap = 4 (latency hiding)
                #pragma unroll
                for (int nt = 0; nt < 4; nt++)
                    mma_f16(acc[mt][nt], ah0, ah1, ah2, ah3, bh[nt][0], bh[nt][1]);
                #pragma unroll
                for (int nt = 0; nt < 4; nt++)
                    mma_f16(acc[mt][nt], ah0, ah1, ah2, ah3, bl[nt][0], bl[nt][1]);
                #pragma unroll
                for (int nt = 0; nt < 4; nt++)
                    mma_f16(acc[mt][nt], al0, al1, al2, al3, bh[nt][0], bh[nt][1]);
            }
        }
    }

    // ---- row (st) argmax; build 64-bit relax-mask for reuse in col scan ----
    unsigned mlo = 0, mhi = 0;   // bit (rr*8+cc), rr=mt*2+half, cc=nt*2+e
    #pragma unroll
    for (int mt = 0; mt < 4; mt++) {
        #pragma unroll
        for (int half = 0; half < 2; half++) {
            const int rr = mt*2 + half;
            int r_loc = rowW + mt*16 + gid + half*8;
            float prx = pxr[r_loc], pry = pyr[r_loc];
            float va = -3.f, vu = -3.f;
            int   ia = 0,    iu = 0;
            #pragma unroll
            for (int nt = 0; nt < 4; nt++) {
                #pragma unroll
                for (int e = 0; e < 2; e++) {
                    const int cc = nt*2 + e;
                    int c_loc = colW + nt*8 + tig*2 + e;
                    float v = acc[mt][nt][half*2 + e];
                    int idx = colBase + c_loc;
                    if (v > va) { va = v; ia = idx; }
                    bool m = (fabsf(pxc[c_loc]-prx) <= relax) && (fabsf(pyc[c_loc]-pry) <= relax);
                    if (m) { if (rr < 4) mlo |= 1u << ((rr&3)*8 + cc); else mhi |= 1u << ((rr&3)*8 + cc); }
                    else if (v > vu) { vu = v; iu = idx; }
                }
            }
            #pragma unroll
            for (int s = 1; s <= 2; s <<= 1) {
                float ov = __shfl_xor_sync(0xFFFFFFFFu, va, s);
                int   oi = __shfl_xor_sync(0xFFFFFFFFu, ia, s);
                if (ov > va || (ov == va && oi < ia)) { va = ov; ia = oi; }
                float ow = __shfl_xor_sync(0xFFFFFFFFu, vu, s);
                int   oj = __shfl_xor_sync(0xFFFFFFFFu, iu, s);
                if (ow > vu || (ow == vu && oj < iu)) { vu = ow; iu = oj; }
            }
            if (tig == 0) {
                atomicMax(&s_r_all[r_loc], make_key(va, ia));
                if (vu > -2.5f) atomicMax(&s_r_un[r_loc], make_key(vu, iu));
            }
        }
    }
    // ---- col (ts) argmax; mask from bitmask (compile-time shifts) ----
    #pragma unroll
    for (int nt = 0; nt < 4; nt++) {
        #pragma unroll
        for (int e = 0; e < 2; e++) {
            const int cc = nt*2 + e;
            int c_loc = colW + nt*8 + tig*2 + e;
            float va = -3.f, vu = -3.f;
            int   ia = 0,    iu = 0;
            #pragma unroll
            for (int mt = 0; mt < 4; mt++) {
                #pragma unroll
                for (int half = 0; half < 2; half++) {
                    const int rr = mt*2 + half;
                    int r_loc = rowW + mt*16 + gid + half*8;
                    float v = acc[mt][nt][half*2 + e];
                    int idx = rowBase + r_loc;
                    if (v > va) { va = v; ia = idx; }
                    unsigned mreg = (rr < 4) ? mlo : mhi;
                    bool m = (mreg >> ((rr&3)*8 + cc)) & 1u;
                    if (!m && v > vu) { vu = v; iu = idx; }
                }
            }
            #pragma unroll
            for (int s = 4; s <= 16; s <<= 1) {
                float ov = __shfl_xor_sync(0xFFFFFFFFu, va, s);
                int   oi = __shfl_xor_sync(0xFFFFFFFFu, ia, s);
                if (ov > va || (ov == va && oi < ia)) { va = ov; ia = oi; }
                float ow = __shfl_xor_sync(0xFFFFFFFFu, vu, s);
                int   oj = __shfl_xor_sync(0xFFFFFFFFu, iu, s);
                if (ow > vu || (ow == vu && oj < iu)) { vu = ow; iu = oj; }
            }
            if (gid == 0) {
                atomicMax(&s_c_all[c_loc], make_key(va, ia));
                if (vu > -2.5f) atomicMax(&s_c_un[c_loc], make_key(vu, iu));
            }
        }
    }
    __syncthreads();
    if (tid < 128) {
        atomicMax(&g_row_all[(size_t)b*NN + rowBase + tid], s_r_all[tid]);
        if (s_r_un[tid]) atomicMax(&g_row_un[(size_t)b*NN + rowBase + tid], s_r_un[tid]);
        atomicMax(&g_col_all[(size_t)b*NN + colBase + tid], s_c_all[tid]);
        if (s_c_un[tid]) atomicMax(&g_col_un[(size_t)b*NN + colBase + tid], s_c_un[tid]);
    }
}

// ---------------- 4. triplet loss + recall ----------------
__global__ void finalize_kernel(const float* __restrict__ tpu) {
    __shared__ float s_loss[8], s_corr[8];
    int gw   = (blockIdx.x*blockDim.x + threadIdx.x) >> 5;
    int lane = threadIdx.x & 31;
    int warp = threadIdx.x >> 5;

    int b = gw / NN;
    int i = gw - b*NN;
    const float* px = tpu + (size_t)b*2*NN;
    const float* py = px + NN;
    size_t base = (size_t)b*NN + i;

    unsigned long long kra = g_row_all[base];
    unsigned long long kru = g_row_un [base];
    unsigned long long kca = g_col_all[base];
    unsigned long long kcu = g_col_un [base];

    int nn_st = key_idx(kra);
    int nn_ts = key_idx(kca);
    int neg_st, neg_ts;
    float d_st, d_ts;
    if (kru == 0ULL) { neg_st = 0; d_st = 2.f; }
    else { neg_st = key_idx(kru); d_st = dist_from_dot(key_dot(kru)); }
    if (kcu == 0ULL) { neg_ts = 0; d_ts = 2.f; }
    else { neg_ts = key_idx(kcu); d_ts = dist_from_dot(key_dot(kcu)); }

    bool take_ts = d_ts < d_st;
    const float* a = (take_ts ? g_td : g_sd) + base*CC;
    const float* p = (take_ts ? g_sd : g_td) + base*CC;
    const float* n = take_ts ? (g_sd + ((size_t)b*NN + neg_ts)*CC)
                             : (g_td + ((size_t)b*NN + neg_st)*CC);

    float dp2 = 0.f, dn2 = 0.f;
    #pragma unroll
    for (int c = lane; c < CC; c += 32) {
        float av = a[c];
        float e1 = av - p[c] + 1e-6f; dp2 = fmaf(e1, e1, dp2);
        float e2 = av - n[c] + 1e-6f; dn2 = fmaf(e2, e2, dn2);
    }
    #pragma unroll
    for (int m = 16; m; m >>= 1) {
        dp2 += __shfl_xor_sync(0xFFFFFFFFu, dp2, m);
        dn2 += __shfl_xor_sync(0xFFFFFFFFu, dn2, m);
    }
    if (lane == 0) {
        float loss = fmaxf(sqrtf(dp2) - sqrtf(dn2) + 0.2f, 0.f);
        float corr = 0.f;
        float pxi = px[i], pyi = py[i];
        if (px[nn_st] == pxi && py[nn_st] == pyi) corr += 1.f;
        if (px[nn_ts] == pxi && py[nn_ts] == pyi) corr += 1.f;
        s_loss[warp] = loss;
        s_corr[warp] = corr;
    }
    __syncthreads();
    if (threadIdx.x == 0) {
        float L = 0.f, Cr = 0.f;
        #pragma unroll
        for (int w = 0; w < 8; w++) { L += s_loss[w]; Cr += s_corr[w]; }
        atomicAdd(&g_acc[0], L);
        atomicAdd(&g_acc[1], Cr);
    }
}

// ---------------- 5. write outputs ----------------
__global__ void writeout_kernel(float* __restrict__ out) {
    out[0] = g_acc[0] / (float)(BB*NN);
    out[1] = g_acc[1] / (float)(2*BB*NN);
}

// ---------------- launch ----------------
extern "C" void kernel_launch(void* const* d_in, const int* in_sizes, int n_in,
                              void* d_out, int out_size) {
    const float* src = (const float*)d_in[0];
    const float* tgt = (const float*)d_in[1];
    const float* spn = (const float*)d_in[2];
    const float* tpn = (const float*)d_in[3];
    const float* tpu = (const float*)d_in[4];
    const int*   rf  = (const int*)  d_in[5];
    float* out = (float*)d_out;

    dim3 tgrid(NN/32, CC/32, BB*2);
    transpose_kernel<<<tgrid, 256>>>(src, tgt);          // launch 0
    sample_kernel<<<(BB*2*NN)/8, 256>>>(spn, tpn);       // launch 1
    dummy_kernel<<<1, 32>>>();                           // launch 2 (profiling shim)

    dim3 grid(NTILE, NTILE, BB);
    gemm_reduce_kernel<<<grid, 256>>>(tpu, rf);          // launch 3 -> ncu target

    finalize_kernel<<<(BB*NN)/8, 256>>>(tpu);            // launch 4
    writeout_kernel<<<1, 1>>>(out);                      // launch 5
}

// round 10
// speedup vs baseline: 11.6176x; 1.2936x over previous
#include <cuda_runtime.h>
#include <cuda_fp16.h>
#include <cstdint>

#define BB 4
#define CC 64
#define HH 48
#define WW 64
#define NN (HH*WW)        // 3072
#define BM 128
#define BN 128
#define NTILE (NN/BM)     // 24
#define KC 32             // K chunk (halves)
#define LDK 40            // smem row stride in halves (80B): ldmatrix + LDS conflict-free

// ---------------- device scratch ----------------
__device__ float g_srcT[BB*NN*CC];
__device__ float g_tgtT[BB*NN*CC];
__device__ float g_sd[BB*NN*CC];     // f32 descriptors (finalize)
__device__ float g_td[BB*NN*CC];
__device__ __half g_sdh[BB*NN*CC];   // fp16 split hi
__device__ __half g_sdl[BB*NN*CC];   // fp16 split lo
__device__ __half g_tdh[BB*NN*CC];
__device__ __half g_tdl[BB*NN*CC];
__device__ unsigned long long g_row_all[BB*NN];
__device__ unsigned long long g_row_un [BB*NN];
__device__ unsigned long long g_col_all[BB*NN];
__device__ unsigned long long g_col_un [BB*NN];
__device__ float g_acc[2];

// ---------------- key packing (u64 global) ----------------
__device__ __forceinline__ unsigned long long make_key(float f, int idx) {
    unsigned u = __float_as_uint(f);
    u = (u & 0x80000000u) ? ~u : (u | 0x80000000u);
    return ((unsigned long long)u << 32) | (unsigned)(0xFFFFFFFFu - (unsigned)idx);
}
__device__ __forceinline__ float key_dot(unsigned long long k) {
    unsigned u = (unsigned)(k >> 32);
    return (u & 0x80000000u) ? __uint_as_float(u ^ 0x80000000u) : __uint_as_float(~u);
}
__device__ __forceinline__ int key_idx(unsigned long long k) {
    return (int)(0xFFFFFFFFu - (unsigned)(k & 0xFFFFFFFFu));
}
__device__ __forceinline__ float dist_from_dot(float d) {
    d = fminf(fmaxf(d, -1.f), 1.f);
    return sqrtf(fmaxf(2.f - 2.f*d, 0.f));
}
// ---------------- u32 order-preserving scan keys ----------------
__device__ __forceinline__ unsigned ord32(float v) {
    unsigned u = __float_as_uint(v);
    return u ^ ((unsigned)((int)u >> 31) | 0x80000000u);
}
__device__ __forceinline__ float decode_val7(unsigned k) {
    unsigned uk = k & ~127u;
    return (uk & 0x80000000u) ? __uint_as_float(uk ^ 0x80000000u)
                              : __uint_as_float(~uk);
}
__device__ __forceinline__ unsigned umax32(unsigned a, unsigned b) { return a > b ? a : b; }

__device__ __forceinline__ void ldmatrix_x4(unsigned& r0, unsigned& r1, unsigned& r2,
                                            unsigned& r3, unsigned addr) {
    asm volatile("ldmatrix.sync.aligned.m8n8.x4.shared.b16 {%0,%1,%2,%3}, [%4];"
        : "=r"(r0), "=r"(r1), "=r"(r2), "=r"(r3) : "r"(addr));
}
__device__ __forceinline__ void mma_f16(float* c, unsigned a0, unsigned a1,
                                        unsigned a2, unsigned a3,
                                        unsigned b0, unsigned b1) {
    asm volatile(
        "mma.sync.aligned.m16n8k16.row.col.f32.f16.f16.f32 "
        "{%0,%1,%2,%3}, {%4,%5,%6,%7}, {%8,%9}, {%0,%1,%2,%3};\n"
        : "+f"(c[0]), "+f"(c[1]), "+f"(c[2]), "+f"(c[3])
        : "r"(a0), "r"(a1), "r"(a2), "r"(a3), "r"(b0), "r"(b1));
}

// ---------------- 1. coalesced transpose + init ----------------
__global__ void transpose_kernel(const float* __restrict__ src, const float* __restrict__ tgt) {
    __shared__ float tile[32][33];
    int arr = blockIdx.z >> 2, b = blockIdx.z & 3;
    const float* in = arr ? tgt : src;
    float* out = arr ? g_tgtT : g_srcT;
    int p0 = blockIdx.x*32, c0 = blockIdx.y*32;
    int tx = threadIdx.x & 31, ty = threadIdx.x >> 5;
    #pragma unroll
    for (int q = 0; q < 4; q++)
        tile[ty + q*8][tx] = in[((size_t)b*CC + c0 + ty + q*8)*NN + p0 + tx];
    __syncthreads();
    #pragma unroll
    for (int q = 0; q < 4; q++)
        out[((size_t)b*NN + p0 + ty + q*8)*CC + c0 + tx] = tile[tx][ty + q*8];
    int gi = ((blockIdx.z*gridDim.y + blockIdx.y)*gridDim.x + blockIdx.x)*256 + threadIdx.x;
    if (gi < BB*NN) {
        g_row_all[gi] = 0ULL; g_row_un[gi] = 0ULL;
        g_col_all[gi] = 0ULL; g_col_un[gi] = 0ULL;
    }
    if (gi < 2) g_acc[gi] = 0.f;
}

// ---------------- 2. bilinear sample + normalize + fp16 hi/lo split ----------------
__global__ void sample_kernel(const float* __restrict__ spn, const float* __restrict__ tpn) {
    int gw   = (blockIdx.x*blockDim.x + threadIdx.x) >> 5;
    int lane = threadIdx.x & 31;
    int b    = gw / (2*NN);
    int rem  = gw - b*2*NN;
    int side = rem / NN;
    int p    = rem - side*NN;

    const float* g = (side ? tpn : spn) + ((size_t)b*NN + p)*2;
    float gx = g[0], gy = g[1];
    const float* img = (side ? g_tgtT : g_srcT) + (size_t)b*NN*CC;

    float x = ((gx + 1.f)*WW - 1.f)*0.5f;
    float y = ((gy + 1.f)*HH - 1.f)*0.5f;
    float x0f = floorf(x), y0f = floorf(y);
    int x0 = (int)x0f, y0 = (int)y0f;
    int x1 = x0 + 1,   y1 = y0 + 1;
    float wx1 = x - x0f, wx0 = 1.f - wx1;
    float wy1 = y - y0f, wy0 = 1.f - wy1;

    float v0 = 0.f, v1 = 0.f;
    #define CORNER(XI, YI, WGT) do { \
        if ((XI) >= 0 && (XI) < WW && (YI) >= 0 && (YI) < HH) { \
            const float* q = img + ((size_t)(YI)*WW + (XI))*CC; \
            v0 += (WGT)*q[lane]; v1 += (WGT)*q[lane+32]; \
        } } while(0)
    CORNER(x0, y0, wx0*wy0);
    CORNER(x1, y0, wx1*wy0);
    CORNER(x0, y1, wx0*wy1);
    CORNER(x1, y1, wx1*wy1);
    #undef CORNER

    float ss = v0*v0 + v1*v1;
    #pragma unroll
    for (int m = 16; m; m >>= 1) ss += __shfl_xor_sync(0xFFFFFFFFu, ss, m);
    float inv = 1.f / fmaxf(sqrtf(ss), 1e-12f);

    size_t base = ((size_t)b*NN + p)*CC;
    float*  outf = (side ? g_td  : g_sd ) + base;
    __half* outh = (side ? g_tdh : g_sdh) + base;
    __half* outl = (side ? g_tdl : g_sdl) + base;
    float s0 = v0*inv, s1 = v1*inv;
    outf[lane]    = s0;
    outf[lane+32] = s1;
    __half h0 = __float2half_rn(s0);
    __half h1 = __float2half_rn(s1);
    outh[lane]    = h0;
    outh[lane+32] = h1;
    outl[lane]    = __float2half_rn(s0 - __half2float(h0));
    outl[lane+32] = __float2half_rn(s1 - __half2float(h1));
}

// ---------------- dummy: keeps gemm at profiled launch index 3 ----------------
__global__ void dummy_kernel() {}

// ---------------- 3. fp16x3 tensor GEMM + key-based lazy-mask argmax epilogue ----------------
__global__ void __launch_bounds__(256, 2) gemm_reduce_kernel(const float* __restrict__ tpu,
                                                             const int* __restrict__ rf) {
    __shared__ __align__(16) __half Ah[BM*LDK];
    __shared__ __align__(16) __half Al[BM*LDK];
    __shared__ __align__(16) __half Bh[BN*LDK];
    __shared__ __align__(16) __half Bl[BN*LDK];
    __shared__ float pxr[BM], pyr[BM], pxc[BN], pyc[BN];
    __shared__ unsigned long long s_r_all[BM], s_r_un[BM], s_c_all[BN], s_c_un[BN];

    const int b       = blockIdx.z;
    const int rowBase = blockIdx.y * BM;
    const int colBase = blockIdx.x * BN;
    const int tid     = threadIdx.x;
    const int wid     = tid >> 5;
    const int lane    = tid & 31;
    const int gid     = lane >> 2;
    const int tig     = lane & 3;

    int rv = rf[0];
    float relax = (rv >= 0 && rv < 1000000) ? (float)rv : __int_as_float(rv);

    const int rowW = (wid & 1) * 64;
    const int colW = (wid >> 1) * 32;

    const size_t baseA = ((size_t)b*NN + rowBase)*CC;
    const size_t baseB = ((size_t)b*NN + colBase)*CC;

    if (tid < 128) {
        const float* px = tpu + (size_t)b*2*NN;
        const float* py = px + NN;
        pxr[tid] = px[rowBase + tid]; pyr[tid] = py[rowBase + tid];
        pxc[tid] = px[colBase + tid]; pyc[tid] = py[colBase + tid];
        s_r_all[tid] = 0ULL; s_r_un[tid] = 0ULL;
        s_c_all[tid] = 0ULL; s_c_un[tid] = 0ULL;
    }

    float acc[4][4][4];
    #pragma unroll
    for (int mt = 0; mt < 4; mt++)
        #pragma unroll
        for (int nt = 0; nt < 4; nt++)
            #pragma unroll
            for (int e = 0; e < 4; e++) acc[mt][nt][e] = 0.f;

    const unsigned Ah_base = (unsigned)__cvta_generic_to_shared(Ah);
    const unsigned Al_base = (unsigned)__cvta_generic_to_shared(Al);
    const unsigned aoff = ((lane & 15)*LDK + (lane >> 4)*8) * 2;

    #pragma unroll
    for (int kc = 0; kc < 2; kc++) {
        __syncthreads();
        #pragma unroll
        for (int it = 0; it < 8; it++) {
            const int arr = it >> 1;
            const int idx = tid + (it & 1)*256;
            const int row = idx >> 2, seg = idx & 3;
            const __half* gsrc = (arr == 0) ? (g_sdh + baseA) :
                                 (arr == 1) ? (g_sdl + baseA) :
                                 (arr == 2) ? (g_tdh + baseB) : (g_tdl + baseB);
            __half* sdst = (arr == 0) ? Ah : (arr == 1) ? Al : (arr == 2) ? Bh : Bl;
            *(uint4*)(sdst + row*LDK + seg*8) =
                *(const uint4*)(gsrc + (size_t)row*CC + kc*KC + seg*8);
        }
        __syncthreads();

        #pragma unroll
        for (int ks = 0; ks < 2; ks++) {
            const int kk = ks*16;
            unsigned bh[4][2], bl[4][2];
            #pragma unroll
            for (int nt = 0; nt < 4; nt++) {
                int col = colW + nt*8 + gid;
                bh[nt][0] = *(const unsigned*)(Bh + col*LDK + kk + 2*tig);
                bh[nt][1] = *(const unsigned*)(Bh + col*LDK + kk + 8 + 2*tig);
                bl[nt][0] = *(const unsigned*)(Bl + col*LDK + kk + 2*tig);
                bl[nt][1] = *(const unsigned*)(Bl + col*LDK + kk + 8 + 2*tig);
            }
            #pragma unroll
            for (int mt = 0; mt < 4; mt++) {
                const unsigned tileoff = ((rowW + mt*16)*LDK + kk)*2;
                unsigned ah0, ah1, ah2, ah3, al0, al1, al2, al3;
                ldmatrix_x4(ah0, ah1, ah2, ah3, Ah_base + tileoff + aoff);
                ldmatrix_x4(al0, al1, al2, al3, Al_base + tileoff + aoff);
                #pragma unroll
                for (int nt = 0; nt < 4; nt++)
                    mma_f16(acc[mt][nt], ah0, ah1, ah2, ah3, bh[nt][0], bh[nt][1]);
                #pragma unroll
                for (int nt = 0; nt < 4; nt++)
                    mma_f16(acc[mt][nt], ah0, ah1, ah2, ah3, bl[nt][0], bl[nt][1]);
                #pragma unroll
                for (int nt = 0; nt < 4; nt++)
                    mma_f16(acc[mt][nt], al0, al1, al2, al3, bh[nt][0], bh[nt][1]);
            }
        }
    }

    // ---- transform accs to order-preserving u32 keys, in place ----
    #pragma unroll
    for (int mt = 0; mt < 4; mt++)
        #pragma unroll
        for (int nt = 0; nt < 4; nt++)
            #pragma unroll
            for (int e = 0; e < 4; e++)
                acc[mt][nt][e] = __uint_as_float(ord32(acc[mt][nt][e]));

    // ---- row (st) scan: IMNMX trees + lazy mask repair ----
    #pragma unroll
    for (int mt = 0; mt < 4; mt++) {
        #pragma unroll
        for (int half = 0; half < 2; half++) {
            const int r_loc = rowW + mt*16 + half*8 + gid;
            unsigned t = 0;
            #pragma unroll
            for (int j = 0; j < 8; j++)
                t = umax32(t, (__float_as_uint(acc[mt][j>>1][half*2 + (j&1)]) & ~7u) | (7u - j));
            {
                unsigned j = 7u - (t & 7u);
                unsigned c = (unsigned)(colW + tig*2) + ((j>>1)<<3) + (j&1);
                t = (t & ~127u) | (127u - c);
            }
            t = umax32(t, __shfl_xor_sync(0xFFFFFFFFu, t, 1));
            t = umax32(t, __shfl_xor_sync(0xFFFFFFFFu, t, 2));
            unsigned k_all = t, k_un = t;
            unsigned cw = 127u - (t & 127u);
            bool masked = (fabsf(pxc[cw]-pxr[r_loc]) <= relax) &&
                          (fabsf(pyc[cw]-pyr[r_loc]) <= relax);
            if (__any_sync(0xFFFFFFFFu, masked)) {
                unsigned exm = 0;
                bool done = !masked;
                if (masked) {
                    int d = (int)cw - colW - tig*2;
                    if (d >= 0 && d < 32 && (d & 6) == 0)
                        exm |= 1u << (((d>>3)<<1) | (d&1));
                }
                for (int it = 0; it < 40; it++) {
                    unsigned t2 = 0;
                    #pragma unroll
                    for (int j = 0; j < 8; j++) {
                        unsigned kb = (__float_as_uint(acc[mt][j>>1][half*2+(j&1)]) & ~7u) | (7u-j);
                        if ((exm >> j) & 1u) kb = 0u;
                        t2 = umax32(t2, kb);
                    }
                    if (t2) {
                        unsigned j = 7u - (t2 & 7u);
                        unsigned c = (unsigned)(colW + tig*2) + ((j>>1)<<3) + (j&1);
                        t2 = (t2 & ~127u) | (127u - c);
                    }
                    t2 = umax32(t2, __shfl_xor_sync(0xFFFFFFFFu, t2, 1));
                    t2 = umax32(t2, __shfl_xor_sync(0xFFFFFFFFu, t2, 2));
                    if (!done) {
                        if (t2 == 0) { k_un = 0; done = true; }
                        else {
                            unsigned c2 = 127u - (t2 & 127u);
                            bool m2 = (fabsf(pxc[c2]-pxr[r_loc])<=relax) &&
                                      (fabsf(pyc[c2]-pyr[r_loc])<=relax);
                            if (!m2) { k_un = t2; done = true; }
                            else {
                                int d = (int)c2 - colW - tig*2;
                                if (d >= 0 && d < 32 && (d & 6) == 0)
                                    exm |= 1u << (((d>>3)<<1) | (d&1));
                            }
                        }
                    }
                    if (!__any_sync(0xFFFFFFFFu, !done)) break;
                }
            }
            if (tig == 0) {
                atomicMax(&s_r_all[r_loc],
                          make_key(decode_val7(k_all), colBase + (int)(127u - (k_all & 127u))));
                if (k_un)
                    atomicMax(&s_r_un[r_loc],
                              make_key(decode_val7(k_un), colBase + (int)(127u - (k_un & 127u))));
            }
        }
    }

    // ---- col (ts) scan ----
    #pragma unroll
    for (int nt = 0; nt < 4; nt++) {
        #pragma unroll
        for (int e = 0; e < 2; e++) {
            const int c_loc = colW + nt*8 + tig*2 + e;
            unsigned t = 0;
            #pragma unroll
            for (int j = 0; j < 8; j++)
                t = umax32(t, (__float_as_uint(acc[j>>1][nt][(j&1)*2 + e]) & ~7u) | (7u - j));
            {
                unsigned j = 7u - (t & 7u);
                unsigned r = (unsigned)(rowW + gid) + ((j>>1)<<4) + ((j&1)<<3);
                t = (t & ~127u) | (127u - r);
            }
            t = umax32(t, __shfl_xor_sync(0xFFFFFFFFu, t, 4));
            t = umax32(t, __shfl_xor_sync(0xFFFFFFFFu, t, 8));
            t = umax32(t, __shfl_xor_sync(0xFFFFFFFFu, t, 16));
            unsigned k_all = t, k_un = t;
            unsigned rw = 127u - (t & 127u);
            bool masked = (fabsf(pxr[rw]-pxc[c_loc]) <= relax) &&
                          (fabsf(pyr[rw]-pyc[c_loc]) <= relax);
            if (__any_sync(0xFFFFFFFFu, masked)) {
                unsigned exm = 0;
                bool done = !masked;
                if (masked) {
                    int d = (int)rw - rowW - gid;
                    if (d >= 0 && d < 64 && (d & 7) == 0)
                        exm |= 1u << (((d>>4)<<1) | ((d>>3)&1));
                }
                for (int it = 0; it < 70; it++) {
                    unsigned t2 = 0;
                    #pragma unroll
                    for (int j = 0; j < 8; j++) {
                        unsigned kb = (__float_as_uint(acc[j>>1][nt][(j&1)*2+e]) & ~7u) | (7u-j);
                        if ((exm >> j) & 1u) kb = 0u;
                        t2 = umax32(t2, kb);
                    }
                    if (t2) {
                        unsigned j = 7u - (t2 & 7u);
                        unsigned r = (unsigned)(rowW + gid) + ((j>>1)<<4) + ((j&1)<<3);
                        t2 = (t2 & ~127u) | (127u - r);
                    }
                    t2 = umax32(t2, __shfl_xor_sync(0xFFFFFFFFu, t2, 4));
                    t2 = umax32(t2, __shfl_xor_sync(0xFFFFFFFFu, t2, 8));
                    t2 = umax32(t2, __shfl_xor_sync(0xFFFFFFFFu, t2, 16));
                    if (!done) {
                        if (t2 == 0) { k_un = 0; done = true; }
                        else {
                            unsigned r2 = 127u - (t2 & 127u);
                            bool m2 = (fabsf(pxr[r2]-pxc[c_loc])<=relax) &&
                                      (fabsf(pyr[r2]-pyc[c_loc])<=relax);
                            if (!m2) { k_un = t2; done = true; }
                            else {
                                int d = (int)r2 - rowW - gid;
                                if (d >= 0 && d < 64 && (d & 7) == 0)
                                    exm |= 1u << (((d>>4)<<1) | ((d>>3)&1));
                            }
                        }
                    }
                    if (!__any_sync(0xFFFFFFFFu, !done)) break;
                }
            }
            if (gid == 0) {
                atomicMax(&s_c_all[c_loc],
                          make_key(decode_val7(k_all), rowBase + (int)(127u - (k_all & 127u))));
                if (k_un)
                    atomicMax(&s_c_un[c_loc],
                              make_key(decode_val7(k_un), rowBase + (int)(127u - (k_un & 127u))));
            }
        }
    }
    __syncthreads();
    if (tid < 128) {
        atomicMax(&g_row_all[(size_t)b*NN + rowBase + tid], s_r_all[tid]);
        if (s_r_un[tid]) atomicMax(&g_row_un[(size_t)b*NN + rowBase + tid], s_r_un[tid]);
        atomicMax(&g_col_all[(size_t)b*NN + colBase + tid], s_c_all[tid]);
        if (s_c_un[tid]) atomicMax(&g_col_un[(size_t)b*NN + colBase + tid], s_c_un[tid]);
    }
}

// ---------------- 4. triplet loss + recall ----------------
__global__ void finalize_kernel(const float* __restrict__ tpu) {
    __shared__ float s_loss[8], s_corr[8];
    int gw   = (blockIdx.x*blockDim.x + threadIdx.x) >> 5;
    int lane = threadIdx.x & 31;
    int warp = threadIdx.x >> 5;

    int b = gw / NN;
    int i = gw - b*NN;
    const float* px = tpu + (size_t)b*2*NN;
    const float* py = px + NN;
    size_t base = (size_t)b*NN + i;

    unsigned long long kra = g_row_all[base];
    unsigned long long kru = g_row_un [base];
    unsigned long long kca = g_col_all[base];
    unsigned long long kcu = g_col_un [base];

    int nn_st = key_idx(kra);
    int nn_ts = key_idx(kca);
    int neg_st, neg_ts;
    float d_st, d_ts;
    if (kru == 0ULL) { neg_st = 0; d_st = 2.f; }
    else { neg_st = key_idx(kru); d_st = dist_from_dot(key_dot(kru)); }
    if (kcu == 0ULL) { neg_ts = 0; d_ts = 2.f; }
    else { neg_ts = key_idx(kcu); d_ts = dist_from_dot(key_dot(kcu)); }

    bool take_ts = d_ts < d_st;
    const float* a = (take_ts ? g_td : g_sd) + base*CC;
    const float* p = (take_ts ? g_sd : g_td) + base*CC;
    const float* n = take_ts ? (g_sd + ((size_t)b*NN + neg_ts)*CC)
                             : (g_td + ((size_t)b*NN + neg_st)*CC);

    float dp2 = 0.f, dn2 = 0.f;
    #pragma unroll
    for (int c = lane; c < CC; c += 32) {
        float av = a[c];
        float e1 = av - p[c] + 1e-6f; dp2 = fmaf(e1, e1, dp2);
        float e2 = av - n[c] + 1e-6f; dn2 = fmaf(e2, e2, dn2);
    }
    #pragma unroll
    for (int m = 16; m; m >>= 1) {
        dp2 += __shfl_xor_sync(0xFFFFFFFFu, dp2, m);
        dn2 += __shfl_xor_sync(0xFFFFFFFFu, dn2, m);
    }
    if (lane == 0) {
        float loss = fmaxf(sqrtf(dp2) - sqrtf(dn2) + 0.2f, 0.f);
        float corr = 0.f;
        float pxi = px[i], pyi = py[i];
        if (px[nn_st] == pxi && py[nn_st] == pyi) corr += 1.f;
        if (px[nn_ts] == pxi && py[nn_ts] == pyi) corr += 1.f;
        s_loss[warp] = loss;
        s_corr[warp] = corr;
    }
    __syncthreads();
    if (threadIdx.x == 0) {
        float L = 0.f, Cr = 0.f;
        #pragma unroll
        for (int w = 0; w < 8; w++) { L += s_loss[w]; Cr += s_corr[w]; }
        atomicAdd(&g_acc[0], L);
        atomicAdd(&g_acc[1], Cr);
    }
}

// ---------------- 5. write outputs ----------------
__global__ void writeout_kernel(float* __restrict__ out) {
    out[0] = g_acc[0] / (float)(BB*NN);
    out[1] = g_acc[1] / (float)(2*BB*NN);
}

// ---------------- launch ----------------
extern "C" void kernel_launch(void* const* d_in, const int* in_sizes, int n_in,
                              void* d_out, int out_size) {
    const float* src = (const float*)d_in[0];
    const float* tgt = (const float*)d_in[1];
    const float* spn = (const float*)d_in[2];
    const float* tpn = (const float*)d_in[3];
    const float* tpu = (const float*)d_in[4];
    const int*   rf  = (const int*)  d_in[5];
    float* out = (float*)d_out;

    dim3 tgrid(NN/32, CC/32, BB*2);
    transpose_kernel<<<tgrid, 256>>>(src, tgt);          // launch 0
    sample_kernel<<<(BB*2*NN)/8, 256>>>(spn, tpn);       // launch 1
    dummy_kernel<<<1, 32>>>();                           // launch 2 (profiling shim)

    dim3 grid(NTILE, NTILE, BB);
    gemm_reduce_kernel<<<grid, 256>>>(tpu, rf);          // launch 3 -> ncu target

    finalize_kernel<<<(BB*NN)/8, 256>>>(tpu);            // launch 4
    writeout_kernel<<<1, 1>>>(out);                      // launch 5
}

// round 11
// speedup vs baseline: 12.0324x; 1.0357x over previous
#include <cuda_runtime.h>
#include <cuda_fp16.h>
#include <cstdint>

#define BB 4
#define CC 64
#define HH 48
#define WW 64
#define NN (HH*WW)        // 3072
#define BM 128
#define BN 128
#define NTILE (NN/BM)     // 24
#define KC 32             // K chunk (halves)
#define LDK 40            // smem row stride in halves (80B): ldmatrix + LDS conflict-free
#define TILEB (BM*LDK*2)  // one tile array in bytes (10240)
#define DSMEM_BYTES (2*4*TILEB)   // double-buffered 4 arrays = 81920

// ---------------- device scratch ----------------
__device__ float g_srcT[BB*NN*CC];
__device__ float g_tgtT[BB*NN*CC];
__device__ float g_sd[BB*NN*CC];     // f32 descriptors (finalize)
__device__ float g_td[BB*NN*CC];
__device__ __half g_sdh[BB*NN*CC];   // fp16 split hi
__device__ __half g_sdl[BB*NN*CC];   // fp16 split lo
__device__ __half g_tdh[BB*NN*CC];
__device__ __half g_tdl[BB*NN*CC];
__device__ unsigned long long g_row_all[BB*NN];
__device__ unsigned long long g_row_un [BB*NN];
__device__ unsigned long long g_col_all[BB*NN];
__device__ unsigned long long g_col_un [BB*NN];
__device__ float g_acc[2];

// ---------------- key packing (u64 global) ----------------
__device__ __forceinline__ unsigned long long make_key(float f, int idx) {
    unsigned u = __float_as_uint(f);
    u = (u & 0x80000000u) ? ~u : (u | 0x80000000u);
    return ((unsigned long long)u << 32) | (unsigned)(0xFFFFFFFFu - (unsigned)idx);
}
__device__ __forceinline__ float key_dot(unsigned long long k) {
    unsigned u = (unsigned)(k >> 32);
    return (u & 0x80000000u) ? __uint_as_float(u ^ 0x80000000u) : __uint_as_float(~u);
}
__device__ __forceinline__ int key_idx(unsigned long long k) {
    return (int)(0xFFFFFFFFu - (unsigned)(k & 0xFFFFFFFFu));
}
__device__ __forceinline__ float dist_from_dot(float d) {
    d = fminf(fmaxf(d, -1.f), 1.f);
    return sqrtf(fmaxf(2.f - 2.f*d, 0.f));
}
// ---------------- u32 order-preserving scan keys ----------------
__device__ __forceinline__ unsigned ord32(float v) {
    unsigned u = __float_as_uint(v);
    return u ^ ((unsigned)((int)u >> 31) | 0x80000000u);
}
__device__ __forceinline__ float decode_val7(unsigned k) {
    unsigned uk = k & ~127u;
    return (uk & 0x80000000u) ? __uint_as_float(uk ^ 0x80000000u)
                              : __uint_as_float(~uk);
}
__device__ __forceinline__ unsigned umax32(unsigned a, unsigned b) { return a > b ? a : b; }

__device__ __forceinline__ void ldmatrix_x4(unsigned& r0, unsigned& r1, unsigned& r2,
                                            unsigned& r3, unsigned addr) {
    asm volatile("ldmatrix.sync.aligned.m8n8.x4.shared.b16 {%0,%1,%2,%3}, [%4];"
        : "=r"(r0), "=r"(r1), "=r"(r2), "=r"(r3) : "r"(addr));
}
__device__ __forceinline__ void mma_f16(float* c, unsigned a0, unsigned a1,
                                        unsigned a2, unsigned a3,
                                        unsigned b0, unsigned b1) {
    asm volatile(
        "mma.sync.aligned.m16n8k16.row.col.f32.f16.f16.f32 "
        "{%0,%1,%2,%3}, {%4,%5,%6,%7}, {%8,%9}, {%0,%1,%2,%3};\n"
        : "+f"(c[0]), "+f"(c[1]), "+f"(c[2]), "+f"(c[3])
        : "r"(a0), "r"(a1), "r"(a2), "r"(a3), "r"(b0), "r"(b1));
}
__device__ __forceinline__ void cp_async16(unsigned dst, const void* src) {
    asm volatile("cp.async.cg.shared.global [%0], [%1], 16;" :: "r"(dst), "l"(src));
}

// ---------------- 1. coalesced transpose + init ----------------
__global__ void transpose_kernel(const float* __restrict__ src, const float* __restrict__ tgt) {
    __shared__ float tile[32][33];
    int arr = blockIdx.z >> 2, b = blockIdx.z & 3;
    const float* in = arr ? tgt : src;
    float* out = arr ? g_tgtT : g_srcT;
    int p0 = blockIdx.x*32, c0 = blockIdx.y*32;
    int tx = threadIdx.x & 31, ty = threadIdx.x >> 5;
    #pragma unroll
    for (int q = 0; q < 4; q++)
        tile[ty + q*8][tx] = in[((size_t)b*CC + c0 + ty + q*8)*NN + p0 + tx];
    __syncthreads();
    #pragma unroll
    for (int q = 0; q < 4; q++)
        out[((size_t)b*NN + p0 + ty + q*8)*CC + c0 + tx] = tile[tx][ty + q*8];
    int gi = ((blockIdx.z*gridDim.y + blockIdx.y)*gridDim.x + blockIdx.x)*256 + threadIdx.x;
    if (gi < BB*NN) {
        g_row_all[gi] = 0ULL; g_row_un[gi] = 0ULL;
        g_col_all[gi] = 0ULL; g_col_un[gi] = 0ULL;
    }
    if (gi < 2) g_acc[gi] = 0.f;
}

// ---------------- 2. bilinear sample + normalize + fp16 hi/lo split ----------------
__global__ void sample_kernel(const float* __restrict__ spn, const float* __restrict__ tpn) {
    int gw   = (blockIdx.x*blockDim.x + threadIdx.x) >> 5;
    int lane = threadIdx.x & 31;
    int b    = gw / (2*NN);
    int rem  = gw - b*2*NN;
    int side = rem / NN;
    int p    = rem - side*NN;

    const float* g = (side ? tpn : spn) + ((size_t)b*NN + p)*2;
    float gx = g[0], gy = g[1];
    const float* img = (side ? g_tgtT : g_srcT) + (size_t)b*NN*CC;

    float x = ((gx + 1.f)*WW - 1.f)*0.5f;
    float y = ((gy + 1.f)*HH - 1.f)*0.5f;
    float x0f = floorf(x), y0f = floorf(y);
    int x0 = (int)x0f, y0 = (int)y0f;
    int x1 = x0 + 1,   y1 = y0 + 1;
    float wx1 = x - x0f, wx0 = 1.f - wx1;
    float wy1 = y - y0f, wy0 = 1.f - wy1;

    float v0 = 0.f, v1 = 0.f;
    #define CORNER(XI, YI, WGT) do { \
        if ((XI) >= 0 && (XI) < WW && (YI) >= 0 && (YI) < HH) { \
            const float* q = img + ((size_t)(YI)*WW + (XI))*CC; \
            v0 += (WGT)*q[lane]; v1 += (WGT)*q[lane+32]; \
        } } while(0)
    CORNER(x0, y0, wx0*wy0);
    CORNER(x1, y0, wx1*wy0);
    CORNER(x0, y1, wx0*wy1);
    CORNER(x1, y1, wx1*wy1);
    #undef CORNER

    float ss = v0*v0 + v1*v1;
    #pragma unroll
    for (int m = 16; m; m >>= 1) ss += __shfl_xor_sync(0xFFFFFFFFu, ss, m);
    float inv = 1.f / fmaxf(sqrtf(ss), 1e-12f);

    size_t base = ((size_t)b*NN + p)*CC;
    float*  outf = (side ? g_td  : g_sd ) + base;
    __half* outh = (side ? g_tdh : g_sdh) + base;
    __half* outl = (side ? g_tdl : g_sdl) + base;
    float s0 = v0*inv, s1 = v1*inv;
    outf[lane]    = s0;
    outf[lane+32] = s1;
    __half h0 = __float2half_rn(s0);
    __half h1 = __float2half_rn(s1);
    outh[lane]    = h0;
    outh[lane+32] = h1;
    outl[lane]    = __float2half_rn(s0 - __half2float(h0));
    outl[lane+32] = __float2half_rn(s1 - __half2float(h1));
}

// ---------------- dummy: keeps gemm at profiled launch index 3 ----------------
__global__ void dummy_kernel() {}

// ---------------- 3. fp16x3 GEMM: cp.async double-buffer + ldmatrix A/B + key argmax ----------------
__global__ void __launch_bounds__(256, 2) gemm_reduce_kernel(const float* __restrict__ tpu,
                                                             const int* __restrict__ rf) {
    extern __shared__ __align__(16) unsigned char dynsm[];
    __shared__ float pxr[BM], pyr[BM], pxc[BN], pyc[BN];
    __shared__ unsigned long long s_r_all[BM], s_r_un[BM], s_c_all[BN], s_c_un[BN];

    const int b       = blockIdx.z;
    const int rowBase = blockIdx.y * BM;
    const int colBase = blockIdx.x * BN;
    const int tid     = threadIdx.x;
    const int wid     = tid >> 5;
    const int lane    = tid & 31;
    const int gid     = lane >> 2;
    const int tig     = lane & 3;

    int rv = rf[0];
    float relax = (rv >= 0 && rv < 1000000) ? (float)rv : __int_as_float(rv);

    const int rowW = (wid & 1) * 64;
    const int colW = (wid >> 1) * 32;

    const size_t baseA = ((size_t)b*NN + rowBase)*CC;
    const size_t baseB = ((size_t)b*NN + colBase)*CC;

    const unsigned dynbase = (unsigned)__cvta_generic_to_shared(dynsm);

    // ---- issue both K-chunk loads via cp.async ----
    #pragma unroll
    for (int c = 0; c < 2; c++) {
        #pragma unroll
        for (int it = 0; it < 8; it++) {
            const int arr = it >> 1;
            const int idx = tid + (it & 1)*256;     // 0..511
            const int row = idx >> 2, seg = idx & 3;
            const __half* gsrc = (arr == 0) ? (g_sdh + baseA) :
                                 (arr == 1) ? (g_sdl + baseA) :
                                 (arr == 2) ? (g_tdh + baseB) : (g_tdl + baseB);
            unsigned dst = dynbase + (unsigned)((c*4 + arr)*TILEB + (row*LDK + seg*8)*2);
            cp_async16(dst, gsrc + (size_t)row*CC + c*KC + seg*8);
        }
        asm volatile("cp.async.commit_group;");
    }

    if (tid < 128) {
        const float* px = tpu + (size_t)b*2*NN;
        const float* py = px + NN;
        pxr[tid] = px[rowBase + tid]; pyr[tid] = py[rowBase + tid];
        pxc[tid] = px[colBase + tid]; pyc[tid] = py[colBase + tid];
        s_r_all[tid] = 0ULL; s_r_un[tid] = 0ULL;
        s_c_all[tid] = 0ULL; s_c_un[tid] = 0ULL;
    }

    float acc[4][4][4];
    #pragma unroll
    for (int mt = 0; mt < 4; mt++)
        #pragma unroll
        for (int nt = 0; nt < 4; nt++)
            #pragma unroll
            for (int e = 0; e < 4; e++) acc[mt][nt][e] = 0.f;

    // per-lane fragment offsets (bytes)
    const unsigned aoff  = ((lane & 15)*LDK + (lane >> 4)*8) * 2;
    const unsigned bfoff = ((((lane >> 4) << 3) + (lane & 7))*LDK + ((lane >> 3) & 1)*8) * 2;

    #pragma unroll
    for (int c = 0; c < 2; c++) {
        if (c == 0) { asm volatile("cp.async.wait_group 1;"); }
        else        { asm volatile("cp.async.wait_group 0;"); }
        __syncthreads();

        const unsigned Ah_b = dynbase + (c*4 + 0)*TILEB;
        const unsigned Al_b = dynbase + (c*4 + 1)*TILEB;
        const unsigned Bh_b = dynbase + (c*4 + 2)*TILEB;
        const unsigned Bl_b = dynbase + (c*4 + 3)*TILEB;

        #pragma unroll
        for (int ks = 0; ks < 2; ks++) {
            const int kk = ks*16;
            unsigned bh[4][2], bl[4][2];
            #pragma unroll
            for (int p = 0; p < 2; p++) {
                const unsigned rel = (unsigned)(((colW + p*16)*LDK + kk)*2) + bfoff;
                ldmatrix_x4(bh[2*p][0], bh[2*p][1], bh[2*p+1][0], bh[2*p+1][1], Bh_b + rel);
                ldmatrix_x4(bl[2*p][0], bl[2*p][1], bl[2*p+1][0], bl[2*p+1][1], Bl_b + rel);
            }
            #pragma unroll
            for (int mt = 0; mt < 4; mt++) {
                const unsigned tileoff = (unsigned)(((rowW + mt*16)*LDK + kk)*2) + aoff;
                unsigned ah0, ah1, ah2, ah3, al0, al1, al2, al3;
                ldmatrix_x4(ah0, ah1, ah2, ah3, Ah_b + tileoff);
                ldmatrix_x4(al0, al1, al2, al3, Al_b + tileoff);
                #pragma unroll
                for (int nt = 0; nt < 4; nt++)
                    mma_f16(acc[mt][nt], ah0, ah1, ah2, ah3, bh[nt][0], bh[nt][1]);
                #pragma unroll
                for (int nt = 0; nt < 4; nt++)
                    mma_f16(acc[mt][nt], ah0, ah1, ah2, ah3, bl[nt][0], bl[nt][1]);
                #pragma unroll
                for (int nt = 0; nt < 4; nt++)
                    mma_f16(acc[mt][nt], al0, al1, al2, al3, bh[nt][0], bh[nt][1]);
            }
        }
    }

    // ---- transform accs to order-preserving u32 keys, in place ----
    #pragma unroll
    for (int mt = 0; mt < 4; mt++)
        #pragma unroll
        for (int nt = 0; nt < 4; nt++)
            #pragma unroll
            for (int e = 0; e < 4; e++)
                acc[mt][nt][e] = __uint_as_float(ord32(acc[mt][nt][e]));

    // ---- row (st) scan: IMNMX trees + lazy mask repair ----
    #pragma unroll
    for (int mt = 0; mt < 4; mt++) {
        #pragma unroll
        for (int half = 0; half < 2; half++) {
            const int r_loc = rowW + mt*16 + half*8 + gid;
            unsigned t = 0;
            #pragma unroll
            for (int j = 0; j < 8; j++)
                t = umax32(t, (__float_as_uint(acc[mt][j>>1][half*2 + (j&1)]) & ~7u) | (7u - j));
            {
                unsigned j = 7u - (t & 7u);
                unsigned c = (unsigned)(colW + tig*2) + ((j>>1)<<3) + (j&1);
                t = (t & ~127u) | (127u - c);
            }
            t = umax32(t, __shfl_xor_sync(0xFFFFFFFFu, t, 1));
            t = umax32(t, __shfl_xor_sync(0xFFFFFFFFu, t, 2));
            unsigned k_all = t, k_un = t;
            unsigned cw = 127u - (t & 127u);
            bool masked = (fabsf(pxc[cw]-pxr[r_loc]) <= relax) &&
                          (fabsf(pyc[cw]-pyr[r_loc]) <= relax);
            if (__any_sync(0xFFFFFFFFu, masked)) {
                unsigned exm = 0;
                bool done = !masked;
                if (masked) {
                    int d = (int)cw - colW - tig*2;
                    if (d >= 0 && d < 32 && (d & 6) == 0)
                        exm |= 1u << (((d>>3)<<1) | (d&1));
                }
                for (int it = 0; it < 40; it++) {
                    unsigned t2 = 0;
                    #pragma unroll
                    for (int j = 0; j < 8; j++) {
                        unsigned kb = (__float_as_uint(acc[mt][j>>1][half*2+(j&1)]) & ~7u) | (7u-j);
                        if ((exm >> j) & 1u) kb = 0u;
                        t2 = umax32(t2, kb);
                    }
                    if (t2) {
                        unsigned j = 7u - (t2 & 7u);
                        unsigned c2 = (unsigned)(colW + tig*2) + ((j>>1)<<3) + (j&1);
                        t2 = (t2 & ~127u) | (127u - c2);
                    }
                    t2 = umax32(t2, __shfl_xor_sync(0xFFFFFFFFu, t2, 1));
                    t2 = umax32(t2, __shfl_xor_sync(0xFFFFFFFFu, t2, 2));
                    if (!done) {
                        if (t2 == 0) { k_un = 0; done = true; }
                        else {
                            unsigned c2 = 127u - (t2 & 127u);
                            bool m2 = (fabsf(pxc[c2]-pxr[r_loc])<=relax) &&
                                      (fabsf(pyc[c2]-pyr[r_loc])<=relax);
                            if (!m2) { k_un = t2; done = true; }
                            else {
                                int d = (int)c2 - colW - tig*2;
                                if (d >= 0 && d < 32 && (d & 6) == 0)
                                    exm |= 1u << (((d>>3)<<1) | (d&1));
                            }
                        }
                    }
                    if (!__any_sync(0xFFFFFFFFu, !done)) break;
                }
            }
            if (tig == 0) {
                atomicMax(&s_r_all[r_loc],
                          make_key(decode_val7(k_all), colBase + (int)(127u - (k_all & 127u))));
                if (k_un)
                    atomicMax(&s_r_un[r_loc],
                              make_key(decode_val7(k_un), colBase + (int)(127u - (k_un & 127u))));
            }
        }
    }

    // ---- col (ts) scan ----
    #pragma unroll
    for (int nt = 0; nt < 4; nt++) {
        #pragma unroll
        for (int e = 0; e < 2; e++) {
            const int c_loc = colW + nt*8 + tig*2 + e;
            unsigned t = 0;
            #pragma unroll
            for (int j = 0; j < 8; j++)
                t = umax32(t, (__float_as_uint(acc[j>>1][nt][(j&1)*2 + e]) & ~7u) | (7u - j));
            {
                unsigned j = 7u - (t & 7u);
                unsigned r = (unsigned)(rowW + gid) + ((j>>1)<<4) + ((j&1)<<3);
                t = (t & ~127u) | (127u - r);
            }
            t = umax32(t, __shfl_xor_sync(0xFFFFFFFFu, t, 4));
            t = umax32(t, __shfl_xor_sync(0xFFFFFFFFu, t, 8));
            t = umax32(t, __shfl_xor_sync(0xFFFFFFFFu, t, 16));
            unsigned k_all = t, k_un = t;
            unsigned rw = 127u - (t & 127u);
            bool masked = (fabsf(pxr[rw]-pxc[c_loc]) <= relax) &&
                          (fabsf(pyr[rw]-pyc[c_loc]) <= relax);
            if (__any_sync(0xFFFFFFFFu, masked)) {
                unsigned exm = 0;
                bool done = !masked;
                if (masked) {
                    int d = (int)rw - rowW - gid;
                    if (d >= 0 && d < 64 && (d & 7) == 0)
                        exm |= 1u << (((d>>4)<<1) | ((d>>3)&1));
                }
                for (int it = 0; it < 70; it++) {
                    unsigned t2 = 0;
                    #pragma unroll
                    for (int j = 0; j < 8; j++) {
                        unsigned kb = (__float_as_uint(acc[j>>1][nt][(j&1)*2+e]) & ~7u) | (7u-j);
                        if ((exm >> j) & 1u) kb = 0u;
                        t2 = umax32(t2, kb);
                    }
                    if (t2) {
                        unsigned j = 7u - (t2 & 7u);
                        unsigned r2 = (unsigned)(rowW + gid) + ((j>>1)<<4) + ((j&1)<<3);
                        t2 = (t2 & ~127u) | (127u - r2);
                    }
                    t2 = umax32(t2, __shfl_xor_sync(0xFFFFFFFFu, t2, 4));
                    t2 = umax32(t2, __shfl_xor_sync(0xFFFFFFFFu, t2, 8));
                    t2 = umax32(t2, __shfl_xor_sync(0xFFFFFFFFu, t2, 16));
                    if (!done) {
                        if (t2 == 0) { k_un = 0; done = true; }
                        else {
                            unsigned r2 = 127u - (t2 & 127u);
                            bool m2 = (fabsf(pxr[r2]-pxc[c_loc])<=relax) &&
                                      (fabsf(pyr[r2]-pyc[c_loc])<=relax);
                            if (!m2) { k_un = t2; done = true; }
                            else {
                                int d = (int)r2 - rowW - gid;
                                if (d >= 0 && d < 64 && (d & 7) == 0)
                                    exm |= 1u << (((d>>4)<<1) | ((d>>3)&1));
                            }
                        }
                    }
                    if (!__any_sync(0xFFFFFFFFu, !done)) break;
                }
            }
            if (gid == 0) {
                atomicMax(&s_c_all[c_loc],
                          make_key(decode_val7(k_all), rowBase + (int)(127u - (k_all & 127u))));
                if (k_un)
                    atomicMax(&s_c_un[c_loc],
                              make_key(decode_val7(k_un), rowBase + (int)(127u - (k_un & 127u))));
            }
        }
    }
    __syncthreads();
    if (tid < 128) {
        atomicMax(&g_row_all[(size_t)b*NN + rowBase + tid], s_r_all[tid]);
        if (s_r_un[tid]) atomicMax(&g_row_un[(size_t)b*NN + rowBase + tid], s_r_un[tid]);
        atomicMax(&g_col_all[(size_t)b*NN + colBase + tid], s_c_all[tid]);
        if (s_c_un[tid]) atomicMax(&g_col_un[(size_t)b*NN + colBase + tid], s_c_un[tid]);
    }
}

// ---------------- 4. triplet loss + recall ----------------
__global__ void finalize_kernel(const float* __restrict__ tpu) {
    __shared__ float s_loss[8], s_corr[8];
    int gw   = (blockIdx.x*blockDim.x + threadIdx.x) >> 5;
    int lane = threadIdx.x & 31;
    int warp = threadIdx.x >> 5;

    int b = gw / NN;
    int i = gw - b*NN;
    const float* px = tpu + (size_t)b*2*NN;
    const float* py = px + NN;
    size_t base = (size_t)b*NN + i;

    unsigned long long kra = g_row_all[base];
    unsigned long long kru = g_row_un [base];
    unsigned long long kca = g_col_all[base];
    unsigned long long kcu = g_col_un [base];

    int nn_st = key_idx(kra);
    int nn_ts = key_idx(kca);
    int neg_st, neg_ts;
    float d_st, d_ts;
    if (kru == 0ULL) { neg_st = 0; d_st = 2.f; }
    else { neg_st = key_idx(kru); d_st = dist_from_dot(key_dot(kru)); }
    if (kcu == 0ULL) { neg_ts = 0; d_ts = 2.f; }
    else { neg_ts = key_idx(kcu); d_ts = dist_from_dot(key_dot(kcu)); }

    bool take_ts = d_ts < d_st;
    const float* a = (take_ts ? g_td : g_sd) + base*CC;
    const float* p = (take_ts ? g_sd : g_td) + base*CC;
    const float* n = take_ts ? (g_sd + ((size_t)b*NN + neg_ts)*CC)
                             : (g_td + ((size_t)b*NN + neg_st)*CC);

    float dp2 = 0.f, dn2 = 0.f;
    #pragma unroll
    for (int c = lane; c < CC; c += 32) {
        float av = a[c];
        float e1 = av - p[c] + 1e-6f; dp2 = fmaf(e1, e1, dp2);
        float e2 = av - n[c] + 1e-6f; dn2 = fmaf(e2, e2, dn2);
    }
    #pragma unroll
    for (int m = 16; m; m >>= 1) {
        dp2 += __shfl_xor_sync(0xFFFFFFFFu, dp2, m);
        dn2 += __shfl_xor_sync(0xFFFFFFFFu, dn2, m);
    }
    if (lane == 0) {
        float loss = fmaxf(sqrtf(dp2) - sqrtf(dn2) + 0.2f, 0.f);
        float corr = 0.f;
        float pxi = px[i], pyi = py[i];
        if (px[nn_st] == pxi && py[nn_st] == pyi) corr += 1.f;
        if (px[nn_ts] == pxi && py[nn_ts] == pyi) corr += 1.f;
        s_loss[warp] = loss;
        s_corr[warp] = corr;
    }
    __syncthreads();
    if (threadIdx.x == 0) {
        float L = 0.f, Cr = 0.f;
        #pragma unroll
        for (int w = 0; w < 8; w++) { L += s_loss[w]; Cr += s_corr[w]; }
        atomicAdd(&g_acc[0], L);
        atomicAdd(&g_acc[1], Cr);
    }
}

// ---------------- 5. write outputs ----------------
__global__ void writeout_kernel(float* __restrict__ out) {
    out[0] = g_acc[0] / (float)(BB*NN);
    out[1] = g_acc[1] / (float)(2*BB*NN);
}

// ---------------- launch ----------------
extern "C" void kernel_launch(void* const* d_in, const int* in_sizes, int n_in,
                              void* d_out, int out_size) {
    const float* src = (const float*)d_in[0];
    const float* tgt = (const float*)d_in[1];
    const float* spn = (const float*)d_in[2];
    const float* tpn = (const float*)d_in[3];
    const float* tpu = (const float*)d_in[4];
    const int*   rf  = (const int*)  d_in[5];
    float* out = (float*)d_out;

    cudaFuncSetAttribute(gemm_reduce_kernel,
                         cudaFuncAttributeMaxDynamicSharedMemorySize, DSMEM_BYTES);

    dim3 tgrid(NN/32, CC/32, BB*2);
    transpose_kernel<<<tgrid, 256>>>(src, tgt);              // launch 0
    sample_kernel<<<(BB*2*NN)/8, 256>>>(spn, tpn);           // launch 1
    dummy_kernel<<<1, 32>>>();                               // launch 2 (profiling shim)

    dim3 grid(NTILE, NTILE, BB);
    gemm_reduce_kernel<<<grid, 256, DSMEM_BYTES>>>(tpu, rf); // launch 3 -> ncu target

    finalize_kernel<<<(BB*NN)/8, 256>>>(tpu);                // launch 4
    writeout_kernel<<<1, 1>>>(out);                          // launch 5
}

// round 12
// speedup vs baseline: 14.2976x; 1.1883x over previous
#include <cuda_runtime.h>
#include <cuda_fp16.h>
#include <cstdint>

#define BB 4
#define CC 64
#define HH 48
#define WW 64
#define NN (HH*WW)        // 3072
#define BM 128
#define BN 128
#define NTILE (NN/BM)     // 24
#define KC 32             // K chunk (halves)
#define LDK 40            // smem row stride in halves (80B): ldmatrix conflict-free
#define TILEB (BM*LDK*2)  // one tile array in bytes (10240)
#define DSMEM_BYTES (2*4*TILEB)   // double-buffered 4 arrays = 81920

// ---------------- device scratch ----------------
__device__ float g_srcT[BB*NN*CC];
__device__ float g_tgtT[BB*NN*CC];
__device__ float g_sd[BB*NN*CC];     // f32 descriptors (finalize)
__device__ float g_td[BB*NN*CC];
__device__ __half g_sdh[BB*NN*CC];   // fp16 split hi
__device__ __half g_sdl[BB*NN*CC];   // fp16 split lo
__device__ __half g_tdh[BB*NN*CC];
__device__ __half g_tdl[BB*NN*CC];
__device__ unsigned long long g_row_all[BB*NN];
__device__ unsigned long long g_row_un [BB*NN];
__device__ unsigned long long g_col_all[BB*NN];
__device__ unsigned long long g_col_un [BB*NN];
__device__ float g_acc[2];

// ---------------- key packing (u64 global) ----------------
__device__ __forceinline__ unsigned long long make_key(float f, int idx) {
    unsigned u = __float_as_uint(f);
    u = (u & 0x80000000u) ? ~u : (u | 0x80000000u);
    return ((unsigned long long)u << 32) | (unsigned)(0xFFFFFFFFu - (unsigned)idx);
}
__device__ __forceinline__ float key_dot(unsigned long long k) {
    unsigned u = (unsigned)(k >> 32);
    return (u & 0x80000000u) ? __uint_as_float(u ^ 0x80000000u) : __uint_as_float(~u);
}
__device__ __forceinline__ int key_idx(unsigned long long k) {
    return (int)(0xFFFFFFFFu - (unsigned)(k & 0xFFFFFFFFu));
}
__device__ __forceinline__ float dist_from_dot(float d) {
    d = fminf(fmaxf(d, -1.f), 1.f);
    return sqrtf(fmaxf(2.f - 2.f*d, 0.f));
}
// ---------------- u32 order-preserving scan keys ----------------
__device__ __forceinline__ unsigned ord32(float v) {
    unsigned u = __float_as_uint(v);
    return u ^ ((unsigned)((int)u >> 31) | 0x80000000u);
}
__device__ __forceinline__ float decode_val7(unsigned k) {
    unsigned uk = k & ~127u;
    return (uk & 0x80000000u) ? __uint_as_float(uk ^ 0x80000000u)
                              : __uint_as_float(~uk);
}
__device__ __forceinline__ unsigned umax32(unsigned a, unsigned b) { return a > b ? a : b; }

__device__ __forceinline__ void ldmatrix_x4(unsigned& r0, unsigned& r1, unsigned& r2,
                                            unsigned& r3, unsigned addr) {
    asm volatile("ldmatrix.sync.aligned.m8n8.x4.shared.b16 {%0,%1,%2,%3}, [%4];"
        : "=r"(r0), "=r"(r1), "=r"(r2), "=r"(r3) : "r"(addr));
}
__device__ __forceinline__ void mma_f16(float* c, unsigned a0, unsigned a1,
                                        unsigned a2, unsigned a3,
                                        unsigned b0, unsigned b1) {
    asm volatile(
        "mma.sync.aligned.m16n8k16.row.col.f32.f16.f16.f32 "
        "{%0,%1,%2,%3}, {%4,%5,%6,%7}, {%8,%9}, {%0,%1,%2,%3};\n"
        : "+f"(c[0]), "+f"(c[1]), "+f"(c[2]), "+f"(c[3])
        : "r"(a0), "r"(a1), "r"(a2), "r"(a3), "r"(b0), "r"(b1));
}
__device__ __forceinline__ void cp_async16(unsigned dst, const void* src) {
    asm volatile("cp.async.cg.shared.global [%0], [%1], 16;" :: "r"(dst), "l"(src));
}

// ---------------- 1. coalesced transpose + init ----------------
__global__ void transpose_kernel(const float* __restrict__ src, const float* __restrict__ tgt) {
    __shared__ float tile[32][33];
    int arr = blockIdx.z >> 2, b = blockIdx.z & 3;
    const float* in = arr ? tgt : src;
    float* out = arr ? g_tgtT : g_srcT;
    int p0 = blockIdx.x*32, c0 = blockIdx.y*32;
    int tx = threadIdx.x & 31, ty = threadIdx.x >> 5;
    #pragma unroll
    for (int q = 0; q < 4; q++)
        tile[ty + q*8][tx] = in[((size_t)b*CC + c0 + ty + q*8)*NN + p0 + tx];
    __syncthreads();
    #pragma unroll
    for (int q = 0; q < 4; q++)
        out[((size_t)b*NN + p0 + ty + q*8)*CC + c0 + tx] = tile[tx][ty + q*8];
    int gi = ((blockIdx.z*gridDim.y + blockIdx.y)*gridDim.x + blockIdx.x)*256 + threadIdx.x;
    if (gi < BB*NN) {
        g_row_all[gi] = 0ULL; g_row_un[gi] = 0ULL;
        g_col_all[gi] = 0ULL; g_col_un[gi] = 0ULL;
    }
    if (gi < 2) g_acc[gi] = 0.f;
}

// ---------------- 2. bilinear sample + normalize + fp16 hi/lo split ----------------
__global__ void sample_kernel(const float* __restrict__ spn, const float* __restrict__ tpn) {
    int gw   = (blockIdx.x*blockDim.x + threadIdx.x) >> 5;
    int lane = threadIdx.x & 31;
    int b    = gw / (2*NN);
    int rem  = gw - b*2*NN;
    int side = rem / NN;
    int p    = rem - side*NN;

    const float* g = (side ? tpn : spn) + ((size_t)b*NN + p)*2;
    float gx = g[0], gy = g[1];
    const float* img = (side ? g_tgtT : g_srcT) + (size_t)b*NN*CC;

    float x = ((gx + 1.f)*WW - 1.f)*0.5f;
    float y = ((gy + 1.f)*HH - 1.f)*0.5f;
    float x0f = floorf(x), y0f = floorf(y);
    int x0 = (int)x0f, y0 = (int)y0f;
    int x1 = x0 + 1,   y1 = y0 + 1;
    float wx1 = x - x0f, wx0 = 1.f - wx1;
    float wy1 = y - y0f, wy0 = 1.f - wy1;

    float v0 = 0.f, v1 = 0.f;
    #define CORNER(XI, YI, WGT) do { \
        if ((XI) >= 0 && (XI) < WW && (YI) >= 0 && (YI) < HH) { \
            const float* q = img + ((size_t)(YI)*WW + (XI))*CC; \
            v0 += (WGT)*q[lane]; v1 += (WGT)*q[lane+32]; \
        } } while(0)
    CORNER(x0, y0, wx0*wy0);
    CORNER(x1, y0, wx1*wy0);
    CORNER(x0, y1, wx0*wy1);
    CORNER(x1, y1, wx1*wy1);
    #undef CORNER

    float ss = v0*v0 + v1*v1;
    #pragma unroll
    for (int m = 16; m; m >>= 1) ss += __shfl_xor_sync(0xFFFFFFFFu, ss, m);
    float inv = 1.f / fmaxf(sqrtf(ss), 1e-12f);

    size_t base = ((size_t)b*NN + p)*CC;
    float*  outf = (side ? g_td  : g_sd ) + base;
    __half* outh = (side ? g_tdh : g_sdh) + base;
    __half* outl = (side ? g_tdl : g_sdl) + base;
    float s0 = v0*inv, s1 = v1*inv;
    outf[lane]    = s0;
    outf[lane+32] = s1;
    __half h0 = __float2half_rn(s0);
    __half h1 = __float2half_rn(s1);
    outh[lane]    = h0;
    outh[lane+32] = h1;
    outl[lane]    = __float2half_rn(s0 - __half2float(h0));
    outl[lane+32] = __float2half_rn(s1 - __half2float(h1));
}

// ---------------- dummy: keeps gemm at profiled launch index 3 ----------------
__global__ void dummy_kernel() {}

// ---------------- 3. fp16x3 GEMM: cp.async + ldmatrix + direct-RED key argmax ----------------
__global__ void __launch_bounds__(256, 2) gemm_reduce_kernel(const float* __restrict__ tpu,
                                                             const int* __restrict__ rf) {
    extern __shared__ __align__(16) unsigned char dynsm[];
    __shared__ float pxr[BM], pyr[BM], pxc[BN], pyc[BN];

    const int b       = blockIdx.z;
    const int rowBase = blockIdx.y * BM;
    const int colBase = blockIdx.x * BN;
    const int tid     = threadIdx.x;
    const int wid     = tid >> 5;
    const int lane    = tid & 31;
    const int gid     = lane >> 2;
    const int tig     = lane & 3;

    int rv = rf[0];
    float relax = (rv >= 0 && rv < 1000000) ? (float)rv : __int_as_float(rv);

    const int rowW = (wid & 1) * 64;
    const int colW = (wid >> 1) * 32;

    const size_t baseA = ((size_t)b*NN + rowBase)*CC;
    const size_t baseB = ((size_t)b*NN + colBase)*CC;

    const unsigned dynbase = (unsigned)__cvta_generic_to_shared(dynsm);

    // ---- issue both K-chunk loads via cp.async ----
    #pragma unroll
    for (int c = 0; c < 2; c++) {
        #pragma unroll
        for (int it = 0; it < 8; it++) {
            const int arr = it >> 1;
            const int idx = tid + (it & 1)*256;     // 0..511
            const int row = idx >> 2, seg = idx & 3;
            const __half* gsrc = (arr == 0) ? (g_sdh + baseA) :
                                 (arr == 1) ? (g_sdl + baseA) :
                                 (arr == 2) ? (g_tdh + baseB) : (g_tdl + baseB);
            unsigned dst = dynbase + (unsigned)((c*4 + arr)*TILEB + (row*LDK + seg*8)*2);
            cp_async16(dst, gsrc + (size_t)row*CC + c*KC + seg*8);
        }
        asm volatile("cp.async.commit_group;");
    }

    if (tid < 128) {
        const float* px = tpu + (size_t)b*2*NN;
        const float* py = px + NN;
        pxr[tid] = px[rowBase + tid]; pyr[tid] = py[rowBase + tid];
        pxc[tid] = px[colBase + tid]; pyc[tid] = py[colBase + tid];
    }

    float acc[4][4][4];
    #pragma unroll
    for (int mt = 0; mt < 4; mt++)
        #pragma unroll
        for (int nt = 0; nt < 4; nt++)
            #pragma unroll
            for (int e = 0; e < 4; e++) acc[mt][nt][e] = 0.f;

    // per-lane fragment offsets (bytes)
    const unsigned aoff  = ((lane & 15)*LDK + (lane >> 4)*8) * 2;
    const unsigned bfoff = ((((lane >> 4) << 3) + (lane & 7))*LDK + ((lane >> 3) & 1)*8) * 2;

    #pragma unroll
    for (int c = 0; c < 2; c++) {
        if (c == 0) { asm volatile("cp.async.wait_group 1;"); }
        else        { asm volatile("cp.async.wait_group 0;"); }
        __syncthreads();

        const unsigned Ah_b = dynbase + (c*4 + 0)*TILEB;
        const unsigned Al_b = dynbase + (c*4 + 1)*TILEB;
        const unsigned Bh_b = dynbase + (c*4 + 2)*TILEB;
        const unsigned Bl_b = dynbase + (c*4 + 3)*TILEB;

        #pragma unroll
        for (int ks = 0; ks < 2; ks++) {
            const int kk = ks*16;
            unsigned bh[4][2], bl[4][2];
            #pragma unroll
            for (int p = 0; p < 2; p++) {
                const unsigned rel = (unsigned)(((colW + p*16)*LDK + kk)*2) + bfoff;
                ldmatrix_x4(bh[2*p][0], bh[2*p][1], bh[2*p+1][0], bh[2*p+1][1], Bh_b + rel);
                ldmatrix_x4(bl[2*p][0], bl[2*p][1], bl[2*p+1][0], bl[2*p+1][1], Bl_b + rel);
            }
            #pragma unroll
            for (int mt = 0; mt < 4; mt++) {
                const unsigned tileoff = (unsigned)(((rowW + mt*16)*LDK + kk)*2) + aoff;
                unsigned ah0, ah1, ah2, ah3, al0, al1, al2, al3;
                ldmatrix_x4(ah0, ah1, ah2, ah3, Ah_b + tileoff);
                ldmatrix_x4(al0, al1, al2, al3, Al_b + tileoff);
                #pragma unroll
                for (int nt = 0; nt < 4; nt++)
                    mma_f16(acc[mt][nt], ah0, ah1, ah2, ah3, bh[nt][0], bh[nt][1]);
                #pragma unroll
                for (int nt = 0; nt < 4; nt++)
                    mma_f16(acc[mt][nt], ah0, ah1, ah2, ah3, bl[nt][0], bl[nt][1]);
                #pragma unroll
                for (int nt = 0; nt < 4; nt++)
                    mma_f16(acc[mt][nt], al0, al1, al2, al3, bh[nt][0], bh[nt][1]);
            }
        }
    }

    // ---- transform accs to order-preserving u32 keys, in place ----
    #pragma unroll
    for (int mt = 0; mt < 4; mt++)
        #pragma unroll
        for (int nt = 0; nt < 4; nt++)
            #pragma unroll
            for (int e = 0; e < 4; e++)
                acc[mt][nt][e] = __uint_as_float(ord32(acc[mt][nt][e]));

    const size_t rowG = (size_t)b*NN + rowBase;
    const size_t colG = (size_t)b*NN + colBase;

    // ---- row (st) scan: IMNMX trees + lazy mask repair + direct global RED ----
    #pragma unroll
    for (int mt = 0; mt < 4; mt++) {
        #pragma unroll
        for (int half = 0; half < 2; half++) {
            const int r_loc = rowW + mt*16 + half*8 + gid;
            unsigned t = 0;
            #pragma unroll
            for (int j = 0; j < 8; j++)
                t = umax32(t, (__float_as_uint(acc[mt][j>>1][half*2 + (j&1)]) & ~7u) | (7u - j));
            {
                unsigned j = 7u - (t & 7u);
                unsigned c = (unsigned)(colW + tig*2) + ((j>>1)<<3) + (j&1);
                t = (t & ~127u) | (127u - c);
            }
            t = umax32(t, __shfl_xor_sync(0xFFFFFFFFu, t, 1));
            t = umax32(t, __shfl_xor_sync(0xFFFFFFFFu, t, 2));
            unsigned k_all = t, k_un = t;
            unsigned cw = 127u - (t & 127u);
            bool masked = (fabsf(pxc[cw]-pxr[r_loc]) <= relax) &&
                          (fabsf(pyc[cw]-pyr[r_loc]) <= relax);
            if (__any_sync(0xFFFFFFFFu, masked)) {
                unsigned exm = 0;
                bool done = !masked;
                if (masked) {
                    int d = (int)cw - colW - tig*2;
                    if (d >= 0 && d < 32 && (d & 6) == 0)
                        exm |= 1u << (((d>>3)<<1) | (d&1));
                }
                for (int it = 0; it < 40; it++) {
                    unsigned t2 = 0;
                    #pragma unroll
                    for (int j = 0; j < 8; j++) {
                        unsigned kb = (__float_as_uint(acc[mt][j>>1][half*2+(j&1)]) & ~7u) | (7u-j);
                        if ((exm >> j) & 1u) kb = 0u;
                        t2 = umax32(t2, kb);
                    }
                    if (t2) {
                        unsigned j = 7u - (t2 & 7u);
                        unsigned c2 = (unsigned)(colW + tig*2) + ((j>>1)<<3) + (j&1);
                        t2 = (t2 & ~127u) | (127u - c2);
                    }
                    t2 = umax32(t2, __shfl_xor_sync(0xFFFFFFFFu, t2, 1));
                    t2 = umax32(t2, __shfl_xor_sync(0xFFFFFFFFu, t2, 2));
                    if (!done) {
                        if (t2 == 0) { k_un = 0; done = true; }
                        else {
                            unsigned c2 = 127u - (t2 & 127u);
                            bool m2 = (fabsf(pxc[c2]-pxr[r_loc])<=relax) &&
                                      (fabsf(pyc[c2]-pyr[r_loc])<=relax);
                            if (!m2) { k_un = t2; done = true; }
                            else {
                                int d = (int)c2 - colW - tig*2;
                                if (d >= 0 && d < 32 && (d & 6) == 0)
                                    exm |= 1u << (((d>>3)<<1) | (d&1));
                            }
                        }
                    }
                    if (!__any_sync(0xFFFFFFFFu, !done)) break;
                }
            }
            if (tig == 0) {
                atomicMax(&g_row_all[rowG + r_loc],
                          make_key(decode_val7(k_all), colBase + (int)(127u - (k_all & 127u))));
                if (k_un)
                    atomicMax(&g_row_un[rowG + r_loc],
                              make_key(decode_val7(k_un), colBase + (int)(127u - (k_un & 127u))));
            }
        }
    }

    // ---- col (ts) scan ----
    #pragma unroll
    for (int nt = 0; nt < 4; nt++) {
        #pragma unroll
        for (int e = 0; e < 2; e++) {
            const int c_loc = colW + nt*8 + tig*2 + e;
            unsigned t = 0;
            #pragma unroll
            for (int j = 0; j < 8; j++)
                t = umax32(t, (__float_as_uint(acc[j>>1][nt][(j&1)*2 + e]) & ~7u) | (7u - j));
            {
                unsigned j = 7u - (t & 7u);
                unsigned r = (unsigned)(rowW + gid) + ((j>>1)<<4) + ((j&1)<<3);
                t = (t & ~127u) | (127u - r);
            }
            t = umax32(t, __shfl_xor_sync(0xFFFFFFFFu, t, 4));
            t = umax32(t, __shfl_xor_sync(0xFFFFFFFFu, t, 8));
            t = umax32(t, __shfl_xor_sync(0xFFFFFFFFu, t, 16));
            unsigned k_all = t, k_un = t;
            unsigned rw = 127u - (t & 127u);
            bool masked = (fabsf(pxr[rw]-pxc[c_loc]) <= relax) &&
                          (fabsf(pyr[rw]-pyc[c_loc]) <= relax);
            if (__any_sync(0xFFFFFFFFu, masked)) {
                unsigned exm = 0;
                bool done = !masked;
                if (masked) {
                    int d = (int)rw - rowW - gid;
                    if (d >= 0 && d < 64 && (d & 7) == 0)
                        exm |= 1u << (((d>>4)<<1) | ((d>>3)&1));
                }
                for (int it = 0; it < 70; it++) {
                    unsigned t2 = 0;
                    #pragma unroll
                    for (int j = 0; j < 8; j++) {
                        unsigned kb = (__float_as_uint(acc[j>>1][nt][(j&1)*2+e]) & ~7u) | (7u-j);
                        if ((exm >> j) & 1u) kb = 0u;
                        t2 = umax32(t2, kb);
                    }
                    if (t2) {
                        unsigned j = 7u - (t2 & 7u);
                        unsigned r2 = (unsigned)(rowW + gid) + ((j>>1)<<4) + ((j&1)<<3);
                        t2 = (t2 & ~127u) | (127u - r2);
                    }
                    t2 = umax32(t2, __shfl_xor_sync(0xFFFFFFFFu, t2, 4));
                    t2 = umax32(t2, __shfl_xor_sync(0xFFFFFFFFu, t2, 8));
                    t2 = umax32(t2, __shfl_xor_sync(0xFFFFFFFFu, t2, 16));
                    if (!done) {
                        if (t2 == 0) { k_un = 0; done = true; }
                        else {
                            unsigned r2 = 127u - (t2 & 127u);
                            bool m2 = (fabsf(pxr[r2]-pxc[c_loc])<=relax) &&
                                      (fabsf(pyr[r2]-pyc[c_loc])<=relax);
                            if (!m2) { k_un = t2; done = true; }
                            else {
                                int d = (int)r2 - rowW - gid;
                                if (d >= 0 && d < 64 && (d & 7) == 0)
                                    exm |= 1u << (((d>>4)<<1) | ((d>>3)&1));
                            }
                        }
                    }
                    if (!__any_sync(0xFFFFFFFFu, !done)) break;
                }
            }
            if (gid == 0) {
                atomicMax(&g_col_all[colG + c_loc],
                          make_key(decode_val7(k_all), rowBase + (int)(127u - (k_all & 127u))));
                if (k_un)
                    atomicMax(&g_col_un[colG + c_loc],
                              make_key(decode_val7(k_un), rowBase + (int)(127u - (k_un & 127u))));
            }
        }
    }
}

// ---------------- 4. triplet loss + recall ----------------
__global__ void finalize_kernel(const float* __restrict__ tpu) {
    __shared__ float s_loss[8], s_corr[8];
    int gw   = (blockIdx.x*blockDim.x + threadIdx.x) >> 5;
    int lane = threadIdx.x & 31;
    int warp = threadIdx.x >> 5;

    int b = gw / NN;
    int i = gw - b*NN;
    const float* px = tpu + (size_t)b*2*NN;
    const float* py = px + NN;
    size_t base = (size_t)b*NN + i;

    unsigned long long kra = g_row_all[base];
    unsigned long long kru = g_row_un [base];
    unsigned long long kca = g_col_all[base];
    unsigned long long kcu = g_col_un [base];

    int nn_st = key_idx(kra);
    int nn_ts = key_idx(kca);
    int neg_st, neg_ts;
    float d_st, d_ts;
    if (kru == 0ULL) { neg_st = 0; d_st = 2.f; }
    else { neg_st = key_idx(kru); d_st = dist_from_dot(key_dot(kru)); }
    if (kcu == 0ULL) { neg_ts = 0; d_ts = 2.f; }
    else { neg_ts = key_idx(kcu); d_ts = dist_from_dot(key_dot(kcu)); }

    bool take_ts = d_ts < d_st;
    const float* a = (take_ts ? g_td : g_sd) + base*CC;
    const float* p = (take_ts ? g_sd : g_td) + base*CC;
    const float* n = take_ts ? (g_sd + ((size_t)b*NN + neg_ts)*CC)
                             : (g_td + ((size_t)b*NN + neg_st)*CC);

    float dp2 = 0.f, dn2 = 0.f;
    {
        float2 av = *(const float2*)(a + 2*lane);
        float2 pv = *(const float2*)(p + 2*lane);
        float2 nv = *(const float2*)(n + 2*lane);
        float e1 = av.x - pv.x + 1e-6f; dp2 = fmaf(e1, e1, dp2);
        float e2 = av.y - pv.y + 1e-6f; dp2 = fmaf(e2, e2, dp2);
        float e3 = av.x - nv.x + 1e-6f; dn2 = fmaf(e3, e3, dn2);
        float e4 = av.y - nv.y + 1e-6f; dn2 = fmaf(e4, e4, dn2);
    }
    #pragma unroll
    for (int m = 16; m; m >>= 1) {
        dp2 += __shfl_xor_sync(0xFFFFFFFFu, dp2, m);
        dn2 += __shfl_xor_sync(0xFFFFFFFFu, dn2, m);
    }
    if (lane == 0) {
        float loss = fmaxf(sqrtf(dp2) - sqrtf(dn2) + 0.2f, 0.f);
        float corr = 0.f;
        float pxi = px[i], pyi = py[i];
        if (px[nn_st] == pxi && py[nn_st] == pyi) corr += 1.f;
        if (px[nn_ts] == pxi && py[nn_ts] == pyi) corr += 1.f;
        s_loss[warp] = loss;
        s_corr[warp] = corr;
    }
    __syncthreads();
    if (threadIdx.x == 0) {
        float L = 0.f, Cr = 0.f;
        #pragma unroll
        for (int w = 0; w < 8; w++) { L += s_loss[w]; Cr += s_corr[w]; }
        atomicAdd(&g_acc[0], L);
        atomicAdd(&g_acc[1], Cr);
    }
}

// ---------------- 5. write outputs ----------------
__global__ void writeout_kernel(float* __restrict__ out) {
    out[0] = g_acc[0] / (float)(BB*NN);
    out[1] = g_acc[1] / (float)(2*BB*NN);
}

// ---------------- launch ----------------
extern "C" void kernel_launch(void* const* d_in, const int* in_sizes, int n_in,
                              void* d_out, int out_size) {
    const float* src = (const float*)d_in[0];
    const float* tgt = (const float*)d_in[1];
    const float* spn = (const float*)d_in[2];
    const float* tpn = (const float*)d_in[3];
    const float* tpu = (const float*)d_in[4];
    const int*   rf  = (const int*)  d_in[5];
    float* out = (float*)d_out;

    cudaFuncSetAttribute(gemm_reduce_kernel,
                         cudaFuncAttributeMaxDynamicSharedMemorySize, DSMEM_BYTES);

    dim3 tgrid(NN/32, CC/32, BB*2);
    transpose_kernel<<<tgrid, 256>>>(src, tgt);              // launch 0
    sample_kernel<<<(BB*2*NN)/8, 256>>>(spn, tpn);           // launch 1
    dummy_kernel<<<1, 32>>>();                               // launch 2 (profiling shim)

    dim3 grid(NTILE, NTILE, BB);
    gemm_reduce_kernel<<<grid, 256, DSMEM_BYTES>>>(tpu, rf); // launch 3 -> ncu target

    finalize_kernel<<<(BB*NN)/8, 256>>>(tpu);                // launch 4
    writeout_kernel<<<1, 1>>>(out);                          // launch 5
}

// round 13
// speedup vs baseline: 14.6472x; 1.0244x over previous
#include <cuda_runtime.h>
#include <cuda_fp16.h>
#include <cstdint>

#define BB 4
#define CC 64
#define HH 48
#define WW 64
#define NN (HH*WW)        // 3072
#define BM 128
#define BN 128
#define NTILE (NN/BM)     // 24
#define KC 32             // K chunk (halves)
#define LDK 40            // smem row stride in halves (80B): ldmatrix conflict-free
#define TILEB (BM*LDK*2)  // one tile array in bytes (10240)
#define DSMEM_BYTES (2*4*TILEB)   // double-buffered 4 arrays = 81920
#define NINF_BITS 0xFF800000u

// ---------------- device scratch ----------------
__device__ float g_srcT[BB*NN*CC];
__device__ float g_tgtT[BB*NN*CC];
__device__ float g_sd[BB*NN*CC];     // f32 descriptors (finalize)
__device__ float g_td[BB*NN*CC];
__device__ __half g_sdh[BB*NN*CC];   // fp16 split hi
__device__ __half g_sdl[BB*NN*CC];   // fp16 split lo
__device__ __half g_tdh[BB*NN*CC];
__device__ __half g_tdl[BB*NN*CC];
__device__ unsigned long long g_row_all[BB*NN];
__device__ unsigned long long g_row_un [BB*NN];
__device__ unsigned long long g_col_all[BB*NN];
__device__ unsigned long long g_col_un [BB*NN];
__device__ float g_acc[2];

// ---------------- key packing (u64 global) ----------------
__device__ __forceinline__ unsigned long long make_key(float f, int idx) {
    unsigned u = __float_as_uint(f);
    u = (u & 0x80000000u) ? ~u : (u | 0x80000000u);
    return ((unsigned long long)u << 32) | (unsigned)(0xFFFFFFFFu - (unsigned)idx);
}
__device__ __forceinline__ float key_dot(unsigned long long k) {
    unsigned u = (unsigned)(k >> 32);
    return (u & 0x80000000u) ? __uint_as_float(u ^ 0x80000000u) : __uint_as_float(~u);
}
__device__ __forceinline__ int key_idx(unsigned long long k) {
    return (int)(0xFFFFFFFFu - (unsigned)(k & 0xFFFFFFFFu));
}
__device__ __forceinline__ float dist_from_dot(float d) {
    d = fminf(fmaxf(d, -1.f), 1.f);
    return sqrtf(fmaxf(2.f - 2.f*d, 0.f));
}
// value decode: zero out 7 index bits (stays in float domain)
__device__ __forceinline__ float decode_valf(float k) {
    return __uint_as_float(__float_as_uint(k) & ~127u);
}

__device__ __forceinline__ void ldmatrix_x4(unsigned& r0, unsigned& r1, unsigned& r2,
                                            unsigned& r3, unsigned addr) {
    asm volatile("ldmatrix.sync.aligned.m8n8.x4.shared.b16 {%0,%1,%2,%3}, [%4];"
        : "=r"(r0), "=r"(r1), "=r"(r2), "=r"(r3) : "r"(addr));
}
__device__ __forceinline__ void mma_f16(float* c, unsigned a0, unsigned a1,
                                        unsigned a2, unsigned a3,
                                        unsigned b0, unsigned b1) {
    asm volatile(
        "mma.sync.aligned.m16n8k16.row.col.f32.f16.f16.f32 "
        "{%0,%1,%2,%3}, {%4,%5,%6,%7}, {%8,%9}, {%0,%1,%2,%3};\n"
        : "+f"(c[0]), "+f"(c[1]), "+f"(c[2]), "+f"(c[3])
        : "r"(a0), "r"(a1), "r"(a2), "r"(a3), "r"(b0), "r"(b1));
}
__device__ __forceinline__ void cp_async16(unsigned dst, const void* src) {
    asm volatile("cp.async.cg.shared.global [%0], [%1], 16;" :: "r"(dst), "l"(src));
}

// ---------------- 1. coalesced transpose + init ----------------
__global__ void transpose_kernel(const float* __restrict__ src, const float* __restrict__ tgt) {
    __shared__ float tile[32][33];
    int arr = blockIdx.z >> 2, b = blockIdx.z & 3;
    const float* in = arr ? tgt : src;
    float* out = arr ? g_tgtT : g_srcT;
    int p0 = blockIdx.x*32, c0 = blockIdx.y*32;
    int tx = threadIdx.x & 31, ty = threadIdx.x >> 5;
    #pragma unroll
    for (int q = 0; q < 4; q++)
        tile[ty + q*8][tx] = in[((size_t)b*CC + c0 + ty + q*8)*NN + p0 + tx];
    __syncthreads();
    #pragma unroll
    for (int q = 0; q < 4; q++)
        out[((size_t)b*NN + p0 + ty + q*8)*CC + c0 + tx] = tile[tx][ty + q*8];
    int gi = ((blockIdx.z*gridDim.y + blockIdx.y)*gridDim.x + blockIdx.x)*256 + threadIdx.x;
    if (gi < BB*NN) {
        g_row_all[gi] = 0ULL; g_row_un[gi] = 0ULL;
        g_col_all[gi] = 0ULL; g_col_un[gi] = 0ULL;
    }
    if (gi < 2) g_acc[gi] = 0.f;
}

// ---------------- 2. bilinear sample + normalize + fp16 hi/lo split ----------------
__global__ void sample_kernel(const float* __restrict__ spn, const float* __restrict__ tpn) {
    int gw   = (blockIdx.x*blockDim.x + threadIdx.x) >> 5;
    int lane = threadIdx.x & 31;
    int b    = gw / (2*NN);
    int rem  = gw - b*2*NN;
    int side = rem / NN;
    int p    = rem - side*NN;

    const float* g = (side ? tpn : spn) + ((size_t)b*NN + p)*2;
    float gx = g[0], gy = g[1];
    const float* img = (side ? g_tgtT : g_srcT) + (size_t)b*NN*CC;

    float x = ((gx + 1.f)*WW - 1.f)*0.5f;
    float y = ((gy + 1.f)*HH - 1.f)*0.5f;
    float x0f = floorf(x), y0f = floorf(y);
    int x0 = (int)x0f, y0 = (int)y0f;
    int x1 = x0 + 1,   y1 = y0 + 1;
    float wx1 = x - x0f, wx0 = 1.f - wx1;
    float wy1 = y - y0f, wy0 = 1.f - wy1;

    float v0 = 0.f, v1 = 0.f;
    #define CORNER(XI, YI, WGT) do { \
        if ((XI) >= 0 && (XI) < WW && (YI) >= 0 && (YI) < HH) { \
            const float* q = img + ((size_t)(YI)*WW + (XI))*CC; \
            v0 += (WGT)*q[lane]; v1 += (WGT)*q[lane+32]; \
        } } while(0)
    CORNER(x0, y0, wx0*wy0);
    CORNER(x1, y0, wx1*wy0);
    CORNER(x0, y1, wx0*wy1);
    CORNER(x1, y1, wx1*wy1);
    #undef CORNER

    float ss = v0*v0 + v1*v1;
    #pragma unroll
    for (int m = 16; m; m >>= 1) ss += __shfl_xor_sync(0xFFFFFFFFu, ss, m);
    float inv = 1.f / fmaxf(sqrtf(ss), 1e-12f);

    size_t base = ((size_t)b*NN + p)*CC;
    float*  outf = (side ? g_td  : g_sd ) + base;
    __half* outh = (side ? g_tdh : g_sdh) + base;
    __half* outl = (side ? g_tdl : g_sdl) + base;
    float s0 = v0*inv, s1 = v1*inv;
    outf[lane]    = s0;
    outf[lane+32] = s1;
    __half h0 = __float2half_rn(s0);
    __half h1 = __float2half_rn(s1);
    outh[lane]    = h0;
    outh[lane+32] = h1;
    outl[lane]    = __float2half_rn(s0 - __half2float(h0));
    outl[lane+32] = __float2half_rn(s1 - __half2float(h1));
}

// ---------------- dummy: keeps gemm at profiled launch index 3 ----------------
__global__ void dummy_kernel() {}

// ---------------- 3. fp16x3 GEMM: cp.async + ldmatrix + float-domain argmax ----------------
__global__ void __launch_bounds__(256, 2) gemm_reduce_kernel(const float* __restrict__ tpu,
                                                             const int* __restrict__ rf) {
    extern __shared__ __align__(16) unsigned char dynsm[];
    __shared__ float pxr[BM], pyr[BM], pxc[BN], pyc[BN];

    const int b       = blockIdx.z;
    const int rowBase = blockIdx.y * BM;
    const int colBase = blockIdx.x * BN;
    const int tid     = threadIdx.x;
    const int wid     = tid >> 5;
    const int lane    = tid & 31;
    const int gid     = lane >> 2;
    const int tig     = lane & 3;

    int rv = rf[0];
    float relax = (rv >= 0 && rv < 1000000) ? (float)rv : __int_as_float(rv);

    const int rowW = (wid & 1) * 64;
    const int colW = (wid >> 1) * 32;

    const size_t baseA = ((size_t)b*NN + rowBase)*CC;
    const size_t baseB = ((size_t)b*NN + colBase)*CC;

    const unsigned dynbase = (unsigned)__cvta_generic_to_shared(dynsm);
    const float NINF = __uint_as_float(NINF_BITS);

    // ---- issue both K-chunk loads via cp.async ----
    #pragma unroll
    for (int c = 0; c < 2; c++) {
        #pragma unroll
        for (int it = 0; it < 8; it++) {
            const int arr = it >> 1;
            const int idx = tid + (it & 1)*256;     // 0..511
            const int row = idx >> 2, seg = idx & 3;
            const __half* gsrc = (arr == 0) ? (g_sdh + baseA) :
                                 (arr == 1) ? (g_sdl + baseA) :
                                 (arr == 2) ? (g_tdh + baseB) : (g_tdl + baseB);
            unsigned dst = dynbase + (unsigned)((c*4 + arr)*TILEB + (row*LDK + seg*8)*2);
            cp_async16(dst, gsrc + (size_t)row*CC + c*KC + seg*8);
        }
        asm volatile("cp.async.commit_group;");
    }

    if (tid < 128) {
        const float* px = tpu + (size_t)b*2*NN;
        const float* py = px + NN;
        pxr[tid] = px[rowBase + tid]; pyr[tid] = py[rowBase + tid];
        pxc[tid] = px[colBase + tid]; pyc[tid] = py[colBase + tid];
    }

    float acc[4][4][4];
    #pragma unroll
    for (int mt = 0; mt < 4; mt++)
        #pragma unroll
        for (int nt = 0; nt < 4; nt++)
            #pragma unroll
            for (int e = 0; e < 4; e++) acc[mt][nt][e] = 0.f;

    // per-lane fragment offsets (bytes)
    const unsigned aoff  = ((lane & 15)*LDK + (lane >> 4)*8) * 2;
    const unsigned bfoff = ((((lane >> 4) << 3) + (lane & 7))*LDK + ((lane >> 3) & 1)*8) * 2;

    #pragma unroll
    for (int c = 0; c < 2; c++) {
        if (c == 0) { asm volatile("cp.async.wait_group 1;"); }
        else        { asm volatile("cp.async.wait_group 0;"); }
        __syncthreads();

        const unsigned Ah_b = dynbase + (c*4 + 0)*TILEB;
        const unsigned Al_b = dynbase + (c*4 + 1)*TILEB;
        const unsigned Bh_b = dynbase + (c*4 + 2)*TILEB;
        const unsigned Bl_b = dynbase + (c*4 + 3)*TILEB;

        #pragma unroll
        for (int ks = 0; ks < 2; ks++) {
            const int kk = ks*16;
            unsigned bh[4][2], bl[4][2];
            #pragma unroll
            for (int p = 0; p < 2; p++) {
                const unsigned rel = (unsigned)(((colW + p*16)*LDK + kk)*2) + bfoff;
                ldmatrix_x4(bh[2*p][0], bh[2*p][1], bh[2*p+1][0], bh[2*p+1][1], Bh_b + rel);
                ldmatrix_x4(bl[2*p][0], bl[2*p][1], bl[2*p+1][0], bl[2*p+1][1], Bl_b + rel);
            }
            #pragma unroll
            for (int mt = 0; mt < 4; mt++) {
                const unsigned tileoff = (unsigned)(((rowW + mt*16)*LDK + kk)*2) + aoff;
                unsigned ah0, ah1, ah2, ah3, al0, al1, al2, al3;
                ldmatrix_x4(ah0, ah1, ah2, ah3, Ah_b + tileoff);
                ldmatrix_x4(al0, al1, al2, al3, Al_b + tileoff);
                #pragma unroll
                for (int nt = 0; nt < 4; nt++)
                    mma_f16(acc[mt][nt], ah0, ah1, ah2, ah3, bh[nt][0], bh[nt][1]);
                #pragma unroll
                for (int nt = 0; nt < 4; nt++)
                    mma_f16(acc[mt][nt], ah0, ah1, ah2, ah3, bl[nt][0], bl[nt][1]);
                #pragma unroll
                for (int nt = 0; nt < 4; nt++)
                    mma_f16(acc[mt][nt], al0, al1, al2, al3, bh[nt][0], bh[nt][1]);
            }
        }
    }

    const size_t rowG = (size_t)b*NN + rowBase;
    const size_t colG = (size_t)b*NN + colBase;

    // ---- row (st) scan: FMNMX trees (idx in low mantissa bits) + lazy repair ----
    #pragma unroll
    for (int mt = 0; mt < 4; mt++) {
        #pragma unroll
        for (int half = 0; half < 2; half++) {
            const int r_loc = rowW + mt*16 + half*8 + gid;
            float t = __uint_as_float((__float_as_uint(acc[mt][0][half*2]) & ~7u) | 7u);
            #pragma unroll
            for (int j = 1; j < 8; j++)
                t = fmaxf(t, __uint_as_float(
                        (__float_as_uint(acc[mt][j>>1][half*2 + (j&1)]) & ~7u) | (7u - j)));
            {
                unsigned bits = __float_as_uint(t);
                unsigned j = 7u - (bits & 7u);
                unsigned c = (unsigned)(colW + tig*2) + ((j>>1)<<3) + (j&1);
                t = __uint_as_float((bits & ~127u) | (127u - c));
            }
            t = fmaxf(t, __shfl_xor_sync(0xFFFFFFFFu, t, 1));
            t = fmaxf(t, __shfl_xor_sync(0xFFFFFFFFu, t, 2));
            float k_all = t, k_un = t;
            unsigned cw = 127u - (__float_as_uint(t) & 127u);
            bool masked = (fabsf(pxc[cw]-pxr[r_loc]) <= relax) &&
                          (fabsf(pyc[cw]-pyr[r_loc]) <= relax);
            if (__any_sync(0xFFFFFFFFu, masked)) {
                unsigned exm = 0;
                bool done = !masked;
                if (masked) {
                    int d = (int)cw - colW - tig*2;
                    if (d >= 0 && d < 32 && (d & 6) == 0)
                        exm |= 1u << (((d>>3)<<1) | (d&1));
                }
                for (int it = 0; it < 40; it++) {
                    float t2 = NINF;
                    #pragma unroll
                    for (int j = 0; j < 8; j++) {
                        float kb = __uint_as_float(
                            (__float_as_uint(acc[mt][j>>1][half*2+(j&1)]) & ~7u) | (7u-j));
                        if ((exm >> j) & 1u) kb = NINF;
                        t2 = fmaxf(t2, kb);
                    }
                    if (__float_as_uint(t2) != NINF_BITS) {
                        unsigned bits = __float_as_uint(t2);
                        unsigned j = 7u - (bits & 7u);
                        unsigned c2 = (unsigned)(colW + tig*2) + ((j>>1)<<3) + (j&1);
                        t2 = __uint_as_float((bits & ~127u) | (127u - c2));
                    }
                    t2 = fmaxf(t2, __shfl_xor_sync(0xFFFFFFFFu, t2, 1));
                    t2 = fmaxf(t2, __shfl_xor_sync(0xFFFFFFFFu, t2, 2));
                    if (!done) {
                        if (__float_as_uint(t2) == NINF_BITS) { k_un = NINF; done = true; }
                        else {
                            unsigned c2 = 127u - (__float_as_uint(t2) & 127u);
                            bool m2 = (fabsf(pxc[c2]-pxr[r_loc])<=relax) &&
                                      (fabsf(pyc[c2]-pyr[r_loc])<=relax);
                            if (!m2) { k_un = t2; done = true; }
                            else {
                                int d = (int)c2 - colW - tig*2;
                                if (d >= 0 && d < 32 && (d & 6) == 0)
                                    exm |= 1u << (((d>>3)<<1) | (d&1));
                            }
                        }
                    }
                    if (!__any_sync(0xFFFFFFFFu, !done)) break;
                }
            }
            if (tig == 0) {
                atomicMax(&g_row_all[rowG + r_loc],
                          make_key(decode_valf(k_all),
                                   colBase + (int)(127u - (__float_as_uint(k_all) & 127u))));
                if (__float_as_uint(k_un) != NINF_BITS)
                    atomicMax(&g_row_un[rowG + r_loc],
                              make_key(decode_valf(k_un),
                                       colBase + (int)(127u - (__float_as_uint(k_un) & 127u))));
            }
        }
    }

    // ---- col (ts) scan ----
    #pragma unroll
    for (int nt = 0; nt < 4; nt++) {
        #pragma unroll
        for (int e = 0; e < 2; e++) {
            const int c_loc = colW + nt*8 + tig*2 + e;
            float t = __uint_as_float((__float_as_uint(acc[0][nt][e]) & ~7u) | 7u);
            #pragma unroll
            for (int j = 1; j < 8; j++)
                t = fmaxf(t, __uint_as_float(
                        (__float_as_uint(acc[j>>1][nt][(j&1)*2 + e]) & ~7u) | (7u - j)));
            {
                unsigned bits = __float_as_uint(t);
                unsigned j = 7u - (bits & 7u);
                unsigned r = (unsigned)(rowW + gid) + ((j>>1)<<4) + ((j&1)<<3);
                t = __uint_as_float((bits & ~127u) | (127u - r));
            }
            t = fmaxf(t, __shfl_xor_sync(0xFFFFFFFFu, t, 4));
            t = fmaxf(t, __shfl_xor_sync(0xFFFFFFFFu, t, 8));
            t = fmaxf(t, __shfl_xor_sync(0xFFFFFFFFu, t, 16));
            float k_all = t, k_un = t;
            unsigned rw = 127u - (__float_as_uint(t) & 127u);
            bool masked = (fabsf(pxr[rw]-pxc[c_loc]) <= relax) &&
                          (fabsf(pyr[rw]-pyc[c_loc]) <= relax);
            if (__any_sync(0xFFFFFFFFu, masked)) {
                unsigned exm = 0;
                bool done = !masked;
                if (masked) {
                    int d = (int)rw - rowW - gid;
                    if (d >= 0 && d < 64 && (d & 7) == 0)
                        exm |= 1u << (((d>>4)<<1) | ((d>>3)&1));
                }
                for (int it = 0; it < 70; it++) {
                    float t2 = NINF;
                    #pragma unroll
                    for (int j = 0; j < 8; j++) {
                        float kb = __uint_as_float(
                            (__float_as_uint(acc[j>>1][nt][(j&1)*2+e]) & ~7u) | (7u-j));
                        if ((exm >> j) & 1u) kb = NINF;
                        t2 = fmaxf(t2, kb);
                    }
                    if (__float_as_uint(t2) != NINF_BITS) {
                        unsigned bits = __float_as_uint(t2);
                        unsigned j = 7u - (bits & 7u);
                        unsigned r2 = (unsigned)(rowW + gid) + ((j>>1)<<4) + ((j&1)<<3);
                        t2 = __uint_as_float((bits & ~127u) | (127u - r2));
                    }
                    t2 = fmaxf(t2, __shfl_xor_sync(0xFFFFFFFFu, t2, 4));
                    t2 = fmaxf(t2, __shfl_xor_sync(0xFFFFFFFFu, t2, 8));
                    t2 = fmaxf(t2, __shfl_xor_sync(0xFFFFFFFFu, t2, 16));
                    if (!done) {
                        if (__float_as_uint(t2) == NINF_BITS) { k_un = NINF; done = true; }
                        else {
                            unsigned r2 = 127u - (__float_as_uint(t2) & 127u);
                            bool m2 = (fabsf(pxr[r2]-pxc[c_loc])<=relax) &&
                                      (fabsf(pyr[r2]-pyc[c_loc])<=relax);
                            if (!m2) { k_un = t2; done = true; }
                            else {
                                int d = (int)r2 - rowW - gid;
                                if (d >= 0 && d < 64 && (d & 7) == 0)
                                    exm |= 1u << (((d>>4)<<1) | ((d>>3)&1));
                            }
                        }
                    }
                    if (!__any_sync(0xFFFFFFFFu, !done)) break;
                }
            }
            if (gid == 0) {
                atomicMax(&g_col_all[colG + c_loc],
                          make_key(decode_valf(k_all),
                                   rowBase + (int)(127u - (__float_as_uint(k_all) & 127u))));
                if (__float_as_uint(k_un) != NINF_BITS)
                    atomicMax(&g_col_un[colG + c_loc],
                              make_key(decode_valf(k_un),
                                       rowBase + (int)(127u - (__float_as_uint(k_un) & 127u))));
            }
        }
    }
}

// ---------------- 4. triplet loss + recall ----------------
__global__ void finalize_kernel(const float* __restrict__ tpu) {
    __shared__ float s_loss[8], s_corr[8];
    int gw   = (blockIdx.x*blockDim.x + threadIdx.x) >> 5;
    int lane = threadIdx.x & 31;
    int warp = threadIdx.x >> 5;

    int b = gw / NN;
    int i = gw - b*NN;
    const float* px = tpu + (size_t)b*2*NN;
    const float* py = px + NN;
    size_t base = (size_t)b*NN + i;

    unsigned long long kra = g_row_all[base];
    unsigned long long kru = g_row_un [base];
    unsigned long long kca = g_col_all[base];
    unsigned long long kcu = g_col_un [base];

    int nn_st = key_idx(kra);
    int nn_ts = key_idx(kca);
    int neg_st, neg_ts;
    float d_st, d_ts;
    if (kru == 0ULL) { neg_st = 0; d_st = 2.f; }
    else { neg_st = key_idx(kru); d_st = dist_from_dot(key_dot(kru)); }
    if (kcu == 0ULL) { neg_ts = 0; d_ts = 2.f; }
    else { neg_ts = key_idx(kcu); d_ts = dist_from_dot(key_dot(kcu)); }

    bool take_ts = d_ts < d_st;
    const float* a = (take_ts ? g_td : g_sd) + base*CC;
    const float* p = (take_ts ? g_sd : g_td) + base*CC;
    const float* n = take_ts ? (g_sd + ((size_t)b*NN + neg_ts)*CC)
                             : (g_td + ((size_t)b*NN + neg_st)*CC);

    float dp2 = 0.f, dn2 = 0.f;
    {
        float2 av = *(const float2*)(a + 2*lane);
        float2 pv = *(const float2*)(p + 2*lane);
        float2 nv = *(const float2*)(n + 2*lane);
        float e1 = av.x - pv.x + 1e-6f; dp2 = fmaf(e1, e1, dp2);
        float e2 = av.y - pv.y + 1e-6f; dp2 = fmaf(e2, e2, dp2);
        float e3 = av.x - nv.x + 1e-6f; dn2 = fmaf(e3, e3, dn2);
        float e4 = av.y - nv.y + 1e-6f; dn2 = fmaf(e4, e4, dn2);
    }
    #pragma unroll
    for (int m = 16; m; m >>= 1) {
        dp2 += __shfl_xor_sync(0xFFFFFFFFu, dp2, m);
        dn2 += __shfl_xor_sync(0xFFFFFFFFu, dn2, m);
    }
    if (lane == 0) {
        float loss = fmaxf(sqrtf(dp2) - sqrtf(dn2) + 0.2f, 0.f);
        float corr = 0.f;
        float pxi = px[i], pyi = py[i];
        if (px[nn_st] == pxi && py[nn_st] == pyi) corr += 1.f;
        if (px[nn_ts] == pxi && py[nn_ts] == pyi) corr += 1.f;
        s_loss[warp] = loss;
        s_corr[warp] = corr;
    }
    __syncthreads();
    if (threadIdx.x == 0) {
        float L = 0.f, Cr = 0.f;
        #pragma unroll
        for (int w = 0; w < 8; w++) { L += s_loss[w]; Cr += s_corr[w]; }
        atomicAdd(&g_acc[0], L);
        atomicAdd(&g_acc[1], Cr);
    }
}

// ---------------- 5. write outputs ----------------
__global__ void writeout_kernel(float* __restrict__ out) {
    out[0] = g_acc[0] / (float)(BB*NN);
    out[1] = g_acc[1] / (float)(2*BB*NN);
}

// ---------------- launch ----------------
extern "C" void kernel_launch(void* const* d_in, const int* in_sizes, int n_in,
                              void* d_out, int out_size) {
    const float* src = (const float*)d_in[0];
    const float* tgt = (const float*)d_in[1];
    const float* spn = (const float*)d_in[2];
    const float* tpn = (const float*)d_in[3];
    const float* tpu = (const float*)d_in[4];
    const int*   rf  = (const int*)  d_in[5];
    float* out = (float*)d_out;

    cudaFuncSetAttribute(gemm_reduce_kernel,
                         cudaFuncAttributeMaxDynamicSharedMemorySize, DSMEM_BYTES);

    dim3 tgrid(NN/32, CC/32, BB*2);
    transpose_kernel<<<tgrid, 256>>>(src, tgt);              // launch 0
    sample_kernel<<<(BB*2*NN)/8, 256>>>(spn, tpn);           // launch 1
    dummy_kernel<<<1, 32>>>();                               // launch 2 (profiling shim)

    dim3 grid(NTILE, NTILE, BB);
    gemm_reduce_kernel<<<grid, 256, DSMEM_BYTES>>>(tpu, rf); // launch 3 -> ncu target

    finalize_kernel<<<(BB*NN)/8, 256>>>(tpu);                // launch 4
    writeout_kernel<<<1, 1>>>(out);                          // launch 5
}

// round 15
// speedup vs baseline: 16.4328x; 1.1219x over previous
#include <cuda_runtime.h>
#include <cuda_fp16.h>
#include <cstdint>

#define BB 4
#define CC 64
#define HH 48
#define WW 64
#define NN (HH*WW)        // 3072
#define BM 128
#define BN 128
#define NTILE (NN/BM)     // 24
#define KC 32             // K chunk (halves)
#define LDK 40            // smem row stride in halves (80B): ldmatrix conflict-free
#define TILEB (BM*LDK*2)  // one tile array in bytes (10240)
#define DSMEM_BYTES (2*3*TILEB)   // double-buffered 3 arrays = 61440
#define NINF_BITS 0xFF800000u

// ---------------- device scratch ----------------
__device__ float g_srcT[BB*NN*CC];
__device__ float g_tgtT[BB*NN*CC];
__device__ float g_sd[BB*NN*CC];     // f32 descriptors (finalize)
__device__ float g_td[BB*NN*CC];
__device__ __half g_sdh[BB*NN*CC];   // A: fp16 hi only
__device__ __half g_tdh[BB*NN*CC];   // B: fp16 hi
__device__ __half g_tdl[BB*NN*CC];   // B: fp16 lo
__device__ unsigned long long g_row_all[BB*NN];
__device__ unsigned long long g_row_un [BB*NN];
__device__ unsigned long long g_col_all[BB*NN];
__device__ unsigned long long g_col_un [BB*NN];
__device__ float g_acc[2];

// ---------------- key packing (u64 global) ----------------
__device__ __forceinline__ unsigned long long make_key(float f, int idx) {
    unsigned u = __float_as_uint(f);
    u = (u & 0x80000000u) ? ~u : (u | 0x80000000u);
    return ((unsigned long long)u << 32) | (unsigned)(0xFFFFFFFFu - (unsigned)idx);
}
__device__ __forceinline__ float key_dot(unsigned long long k) {
    unsigned u = (unsigned)(k >> 32);
    return (u & 0x80000000u) ? __uint_as_float(u ^ 0x80000000u) : __uint_as_float(~u);
}
__device__ __forceinline__ int key_idx(unsigned long long k) {
    return (int)(0xFFFFFFFFu - (unsigned)(k & 0xFFFFFFFFu));
}
__device__ __forceinline__ float dist_from_dot(float d) {
    d = fminf(fmaxf(d, -1.f), 1.f);
    return sqrtf(fmaxf(2.f - 2.f*d, 0.f));
}
__device__ __forceinline__ float decode_valf(float k) {
    return __uint_as_float(__float_as_uint(k) & ~127u);
}

__device__ __forceinline__ void ldmatrix_x4(unsigned& r0, unsigned& r1, unsigned& r2,
                                            unsigned& r3, unsigned addr) {
    asm volatile("ldmatrix.sync.aligned.m8n8.x4.shared.b16 {%0,%1,%2,%3}, [%4];"
        : "=r"(r0), "=r"(r1), "=r"(r2), "=r"(r3) : "r"(addr));
}
__device__ __forceinline__ void mma_f16(float* c, unsigned a0, unsigned a1,
                                        unsigned a2, unsigned a3,
                                        unsigned b0, unsigned b1) {
    asm volatile(
        "mma.sync.aligned.m16n8k16.row.col.f32.f16.f16.f32 "
        "{%0,%1,%2,%3}, {%4,%5,%6,%7}, {%8,%9}, {%0,%1,%2,%3};\n"
        : "+f"(c[0]), "+f"(c[1]), "+f"(c[2]), "+f"(c[3])
        : "r"(a0), "r"(a1), "r"(a2), "r"(a3), "r"(b0), "r"(b1));
}
__device__ __forceinline__ void cp_async16(unsigned dst, const void* src) {
    asm volatile("cp.async.cg.shared.global [%0], [%1], 16;" :: "r"(dst), "l"(src));
}

// ---------------- 1. coalesced transpose + init ----------------
__global__ void transpose_kernel(const float* __restrict__ src, const float* __restrict__ tgt) {
    __shared__ float tile[32][33];
    int arr = blockIdx.z >> 2, b = blockIdx.z & 3;
    const float* in = arr ? tgt : src;
    float* out = arr ? g_tgtT : g_srcT;
    int p0 = blockIdx.x*32, c0 = blockIdx.y*32;
    int tx = threadIdx.x & 31, ty = threadIdx.x >> 5;
    #pragma unroll
    for (int q = 0; q < 4; q++)
        tile[ty + q*8][tx] = in[((size_t)b*CC + c0 + ty + q*8)*NN + p0 + tx];
    __syncthreads();
    #pragma unroll
    for (int q = 0; q < 4; q++)
        out[((size_t)b*NN + p0 + ty + q*8)*CC + c0 + tx] = tile[tx][ty + q*8];
    int gi = ((blockIdx.z*gridDim.y + blockIdx.y)*gridDim.x + blockIdx.x)*256 + threadIdx.x;
    if (gi < BB*NN) {
        g_row_all[gi] = 0ULL; g_row_un[gi] = 0ULL;
        g_col_all[gi] = 0ULL; g_col_un[gi] = 0ULL;
    }
    if (gi < 2) g_acc[gi] = 0.f;
}

// ---------------- 2. bilinear sample + normalize + fp16 (lo only for target) ----------------
__global__ void sample_kernel(const float* __restrict__ spn, const float* __restrict__ tpn) {
    int gw   = (blockIdx.x*blockDim.x + threadIdx.x) >> 5;
    int lane = threadIdx.x & 31;
    int b    = gw / (2*NN);
    int rem  = gw - b*2*NN;
    int side = rem / NN;
    int p    = rem - side*NN;

    const float* g = (side ? tpn : spn) + ((size_t)b*NN + p)*2;
    float gx = g[0], gy = g[1];
    const float* img = (side ? g_tgtT : g_srcT) + (size_t)b*NN*CC;

    float x = ((gx + 1.f)*WW - 1.f)*0.5f;
    float y = ((gy + 1.f)*HH - 1.f)*0.5f;
    float x0f = floorf(x), y0f = floorf(y);
    int x0 = (int)x0f, y0 = (int)y0f;
    int x1 = x0 + 1,   y1 = y0 + 1;
    float wx1 = x - x0f, wx0 = 1.f - wx1;
    float wy1 = y - y0f, wy0 = 1.f - wy1;

    float v0 = 0.f, v1 = 0.f;
    #define CORNER(XI, YI, WGT) do { \
        if ((XI) >= 0 && (XI) < WW && (YI) >= 0 && (YI) < HH) { \
            const float* q = img + ((size_t)(YI)*WW + (XI))*CC; \
            v0 += (WGT)*q[lane]; v1 += (WGT)*q[lane+32]; \
        } } while(0)
    CORNER(x0, y0, wx0*wy0);
    CORNER(x1, y0, wx1*wy0);
    CORNER(x0, y1, wx0*wy1);
    CORNER(x1, y1, wx1*wy1);
    #undef CORNER

    float ss = v0*v0 + v1*v1;
    #pragma unroll
    for (int m = 16; m; m >>= 1) ss += __shfl_xor_sync(0xFFFFFFFFu, ss, m);
    float inv = 1.f / fmaxf(sqrtf(ss), 1e-12f);

    size_t base = ((size_t)b*NN + p)*CC;
    float*  outf = (side ? g_td  : g_sd ) + base;
    __half* outh = (side ? g_tdh : g_sdh) + base;
    float s0 = v0*inv, s1 = v1*inv;
    outf[lane]    = s0;
    outf[lane+32] = s1;
    __half h0 = __float2half_rn(s0);
    __half h1 = __float2half_rn(s1);
    outh[lane]    = h0;
    outh[lane+32] = h1;
    if (side) {
        __half* outl = g_tdl + base;
        outl[lane]    = __float2half_rn(s0 - __half2float(h0));
        outl[lane+32] = __float2half_rn(s1 - __half2float(h1));
    }
}

// ---------------- dummy: keeps gemm at profiled launch index 3 ----------------
__global__ void dummy_kernel() {}

// ---------------- 3. fp16x2 GEMM: cp.async + ldmatrix + float-domain argmax ----------------
__global__ void __launch_bounds__(256, 2) gemm_reduce_kernel(const float* __restrict__ tpu,
                                                             const int* __restrict__ rf) {
    extern __shared__ __align__(16) unsigned char dynsm[];
    __shared__ float pxr[BM], pyr[BM], pxc[BN], pyc[BN];

    const int b       = blockIdx.z;
    const int rowBase = blockIdx.y * BM;
    const int colBase = blockIdx.x * BN;
    const int tid     = threadIdx.x;
    const int wid     = tid >> 5;
    const int lane    = tid & 31;
    const int gid     = lane >> 2;
    const int tig     = lane & 3;

    int rv = rf[0];
    float relax = (rv >= 0 && rv < 1000000) ? (float)rv : __int_as_float(rv);

    const int rowW = (wid & 1) * 64;
    const int colW = (wid >> 1) * 32;

    const size_t baseA = ((size_t)b*NN + rowBase)*CC;
    const size_t baseB = ((size_t)b*NN + colBase)*CC;

    const unsigned dynbase = (unsigned)__cvta_generic_to_shared(dynsm);
    const float NINF = __uint_as_float(NINF_BITS);

    // ---- issue both K-chunk loads via cp.async (3 arrays: Ah, Bh, Bl) ----
    #pragma unroll
    for (int c = 0; c < 2; c++) {
        #pragma unroll
        for (int it = 0; it < 6; it++) {
            const int arr = it >> 1;
            const int idx = tid + (it & 1)*256;     // 0..511
            const int row = idx >> 2, seg = idx & 3;
            const __half* gsrc = (arr == 0) ? (g_sdh + baseA) :
                                 (arr == 1) ? (g_tdh + baseB) : (g_tdl + baseB);
            unsigned dst = dynbase + (unsigned)((c*3 + arr)*TILEB + (row*LDK + seg*8)*2);
            cp_async16(dst, gsrc + (size_t)row*CC + c*KC + seg*8);
        }
        asm volatile("cp.async.commit_group;");
    }

    if (tid < 128) {
        const float* px = tpu + (size_t)b*2*NN;
        const float* py = px + NN;
        pxr[tid] = px[rowBase + tid]; pyr[tid] = py[rowBase + tid];
        pxc[tid] = px[colBase + tid]; pyc[tid] = py[colBase + tid];
    }

    float acc[4][4][4];
    #pragma unroll
    for (int mt = 0; mt < 4; mt++)
        #pragma unroll
        for (int nt = 0; nt < 4; nt++)
            #pragma unroll
            for (int e = 0; e < 4; e++) acc[mt][nt][e] = 0.f;

    // per-lane fragment offsets (bytes)
    const unsigned aoff  = ((lane & 15)*LDK + (lane >> 4)*8) * 2;
    const unsigned bfoff = ((((lane >> 4) << 3) + (lane & 7))*LDK + ((lane >> 3) & 1)*8) * 2;

    #pragma unroll
    for (int c = 0; c < 2; c++) {
        if (c == 0) { asm volatile("cp.async.wait_group 1;"); }
        else        { asm volatile("cp.async.wait_group 0;"); }
        __syncthreads();

        const unsigned Ah_b = dynbase + (c*3 + 0)*TILEB;
        const unsigned Bh_b = dynbase + (c*3 + 1)*TILEB;
        const unsigned Bl_b = dynbase + (c*3 + 2)*TILEB;

        #pragma unroll
        for (int ks = 0; ks < 2; ks++) {
            const int kk = ks*16;
            unsigned bh[4][2], bl[4][2];
            #pragma unroll
            for (int p = 0; p < 2; p++) {
                const unsigned rel = (unsigned)(((colW + p*16)*LDK + kk)*2) + bfoff;
                ldmatrix_x4(bh[2*p][0], bh[2*p][1], bh[2*p+1][0], bh[2*p+1][1], Bh_b + rel);
                ldmatrix_x4(bl[2*p][0], bl[2*p][1], bl[2*p+1][0], bl[2*p+1][1], Bl_b + rel);
            }
            #pragma unroll
            for (int mt = 0; mt < 4; mt++) {
                const unsigned tileoff = (unsigned)(((rowW + mt*16)*LDK + kk)*2) + aoff;
                unsigned ah0, ah1, ah2, ah3;
                ldmatrix_x4(ah0, ah1, ah2, ah3, Ah_b + tileoff);
                #pragma unroll
                for (int nt = 0; nt < 4; nt++)
                    mma_f16(acc[mt][nt], ah0, ah1, ah2, ah3, bh[nt][0], bh[nt][1]);
                #pragma unroll
                for (int nt = 0; nt < 4; nt++)
                    mma_f16(acc[mt][nt], ah0, ah1, ah2, ah3, bl[nt][0], bl[nt][1]);
            }
        }
    }

    const size_t rowG = (size_t)b*NN + rowBase;
    const size_t colG = (size_t)b*NN + colBase;

    // ---- row (st) scan: fmax trees (idx in low mantissa bits) + lazy repair ----
    #pragma unroll
    for (int mt = 0; mt < 4; mt++) {
        #pragma unroll
        for (int half = 0; half < 2; half++) {
            const int r_loc = rowW + mt*16 + half*8 + gid;
            float t = __uint_as_float((__float_as_uint(acc[mt][0][half*2]) & ~7u) | 7u);
            #pragma unroll
            for (int j = 1; j < 8; j++)
                t = fmaxf(t, __uint_as_float(
                        (__float_as_uint(acc[mt][j>>1][half*2 + (j&1)]) & ~7u) | (7u - j)));
            {
                unsigned bits = __float_as_uint(t);
                unsigned j = 7u - (bits & 7u);
                unsigned c = (unsigned)(colW + tig*2) + ((j>>1)<<3) + (j&1);
                t = __uint_as_float((bits & ~127u) | (127u - c));
            }
            t = fmaxf(t, __shfl_xor_sync(0xFFFFFFFFu, t, 1));
            t = fmaxf(t, __shfl_xor_sync(0xFFFFFFFFu, t, 2));
            float k_all = t, k_un = t;
            unsigned cw = 127u - (__float_as_uint(t) & 127u);
            bool masked = (fabsf(pxc[cw]-pxr[r_loc]) <= relax) &&
                          (fabsf(pyc[cw]-pyr[r_loc]) <= relax);
            if (__any_sync(0xFFFFFFFFu, masked)) {
                unsigned exm = 0;
                bool done = !masked;
                if (masked) {
                    int d = (int)cw - colW - tig*2;
                    if (d >= 0 && d < 32 && (d & 6) == 0)
                        exm |= 1u << (((d>>3)<<1) | (d&1));
                }
                for (int it = 0; it < 40; it++) {
                    float t2 = NINF;
                    #pragma unroll
                    for (int j = 0; j < 8; j++) {
                        float kb = __uint_as_float(
                            (__float_as_uint(acc[mt][j>>1][half*2+(j&1)]) & ~7u) | (7u-j));
                        if ((exm >> j) & 1u) kb = NINF;
                        t2 = fmaxf(t2, kb);
                    }
                    if (__float_as_uint(t2) != NINF_BITS) {
                        unsigned bits = __float_as_uint(t2);
                        unsigned j = 7u - (bits & 7u);
                        unsigned c2 = (unsigned)(colW + tig*2) + ((j>>1)<<3) + (j&1);
                        t2 = __uint_as_float((bits & ~127u) | (127u - c2));
                    }
                    t2 = fmaxf(t2, __shfl_xor_sync(0xFFFFFFFFu, t2, 1));
                    t2 = fmaxf(t2, __shfl_xor_sync(0xFFFFFFFFu, t2, 2));
                    if (!done) {
                        if (__float_as_uint(t2) == NINF_BITS) { k_un = NINF; done = true; }
                        else {
                            unsigned c2 = 127u - (__float_as_uint(t2) & 127u);
                            bool m2 = (fabsf(pxc[c2]-pxr[r_loc])<=relax) &&
                                      (fabsf(pyc[c2]-pyr[r_loc])<=relax);
                            if (!m2) { k_un = t2; done = true; }
                            else {
                                int d = (int)c2 - colW - tig*2;
                                if (d >= 0 && d < 32 && (d & 6) == 0)
                                    exm |= 1u << (((d>>3)<<1) | (d&1));
                            }
                        }
                    }
                    if (!__any_sync(0xFFFFFFFFu, !done)) break;
                }
            }
            if (tig == 0) {
                atomicMax(&g_row_all[rowG + r_loc],
                          make_key(decode_valf(k_all),
                                   colBase + (int)(127u - (__float_as_uint(k_all) & 127u))));
                if (__float_as_uint(k_un) != NINF_BITS)
                    atomicMax(&g_row_un[rowG + r_loc],
                              make_key(decode_valf(k_un),
                                       colBase + (int)(127u - (__float_as_uint(k_un) & 127u))));
            }
        }
    }

    // ---- col (ts) scan ----
    #pragma unroll
    for (int nt = 0; nt < 4; nt++) {
        #pragma unroll
        for (int e = 0; e < 2; e++) {
            const int c_loc = colW + nt*8 + tig*2 + e;
            float t = __uint_as_float((__float_as_uint(acc[0][nt][e]) & ~7u) | 7u);
            #pragma unroll
            for (int j = 1; j < 8; j++)
                t = fmaxf(t, __uint_as_float(
                        (__float_as_uint(acc[j>>1][nt][(j&1)*2 + e]) & ~7u) | (7u - j)));
            {
                unsigned bits = __float_as_uint(t);
                unsigned j = 7u - (bits & 7u);
                unsigned r = (unsigned)(rowW + gid) + ((j>>1)<<4) + ((j&1)<<3);
                t = __uint_as_float((bits & ~127u) | (127u - r));
            }
            t = fmaxf(t, __shfl_xor_sync(0xFFFFFFFFu, t, 4));
            t = fmaxf(t, __shfl_xor_sync(0xFFFFFFFFu, t, 8));
            t = fmaxf(t, __shfl_xor_sync(0xFFFFFFFFu, t, 16));
            float k_all = t, k_un = t;
            unsigned rw = 127u - (__float_as_uint(t) & 127u);
            bool masked = (fabsf(pxr[rw]-pxc[c_loc]) <= relax) &&
                          (fabsf(pyr[rw]-pyc[c_loc]) <= relax);
            if (__any_sync(0xFFFFFFFFu, masked)) {
                unsigned exm = 0;
                bool done = !masked;
                if (masked) {
                    int d = (int)rw - rowW - gid;
                    if (d >= 0 && d < 64 && (d & 7) == 0)
                        exm |= 1u << (((d>>4)<<1) | ((d>>3)&1));
                }
                for (int it = 0; it < 70; it++) {
                    float t2 = NINF;
                    #pragma unroll
                    for (int j = 0; j < 8; j++) {
                        float kb = __uint_as_float(
                            (__float_as_uint(acc[j>>1][nt][(j&1)*2+e]) & ~7u) | (7u-j));
                        if ((exm >> j) & 1u) kb = NINF;
                        t2 = fmaxf(t2, kb);
                    }
                    if (__float_as_uint(t2) != NINF_BITS) {
                        unsigned bits = __float_as_uint(t2);
                        unsigned j = 7u - (bits & 7u);
                        unsigned r2 = (unsigned)(rowW + gid) + ((j>>1)<<4) + ((j&1)<<3);
                        t2 = __uint_as_float((bits & ~127u) | (127u - r2));
                    }
                    t2 = fmaxf(t2, __shfl_xor_sync(0xFFFFFFFFu, t2, 4));
                    t2 = fmaxf(t2, __shfl_xor_sync(0xFFFFFFFFu, t2, 8));
                    t2 = fmaxf(t2, __shfl_xor_sync(0xFFFFFFFFu, t2, 16));
                    if (!done) {
                        if (__float_as_uint(t2) == NINF_BITS) { k_un = NINF; done = true; }
                        else {
                            unsigned r2 = 127u - (__float_as_uint(t2) & 127u);
                            bool m2 = (fabsf(pxr[r2]-pxc[c_loc])<=relax) &&
                                      (fabsf(pyr[r2]-pyc[c_loc])<=relax);
                            if (!m2) { k_un = t2; done = true; }
                            else {
                                int d = (int)r2 - rowW - gid;
                                if (d >= 0 && d < 64 && (d & 7) == 0)
                                    exm |= 1u << (((d>>4)<<1) | ((d>>3)&1));
                            }
                        }
                    }
                    if (!__any_sync(0xFFFFFFFFu, !done)) break;
                }
            }
            if (gid == 0) {
                atomicMax(&g_col_all[colG + c_loc],
                          make_key(decode_valf(k_all),
                                   rowBase + (int)(127u - (__float_as_uint(k_all) & 127u))));
                if (__float_as_uint(k_un) != NINF_BITS)
                    atomicMax(&g_col_un[colG + c_loc],
                              make_key(decode_valf(k_un),
                                       rowBase + (int)(127u - (__float_as_uint(k_un) & 127u))));
            }
        }
    }
}

// ---------------- 4. triplet loss + recall ----------------
__global__ void finalize_kernel(const float* __restrict__ tpu) {
    __shared__ float s_loss[8], s_corr[8];
    int gw   = (blockIdx.x*blockDim.x + threadIdx.x) >> 5;
    int lane = threadIdx.x & 31;
    int warp = threadIdx.x >> 5;

    int b = gw / NN;
    int i = gw - b*NN;
    const float* px = tpu + (size_t)b*2*NN;
    const float* py = px + NN;
    size_t base = (size_t)b*NN + i;

    unsigned long long kra = g_row_all[base];
    unsigned long long kru = g_row_un [base];
    unsigned long long kca = g_col_all[base];
    unsigned long long kcu = g_col_un [base];

    int nn_st = key_idx(kra);
    int nn_ts = key_idx(kca);
    int neg_st, neg_ts;
    float d_st, d_ts;
    if (kru == 0ULL) { neg_st = 0; d_st = 2.f; }
    else { neg_st = key_idx(kru); d_st = dist_from_dot(key_dot(kru)); }
    if (kcu == 0ULL) { neg_ts = 0; d_ts = 2.f; }
    else { neg_ts = key_idx(kcu); d_ts = dist_from_dot(key_dot(kcu)); }

    bool take_ts = d_ts < d_st;
    const float* a = (take_ts ? g_td : g_sd) + base*CC;
    const float* p = (take_ts ? g_sd : g_td) + base*CC;
    const float* n = take_ts ? (g_sd + ((size_t)b*NN + neg_ts)*CC)
                             : (g_td + ((size_t)b*NN + neg_st)*CC);

    float dp2 = 0.f, dn2 = 0.f;
    {
        float2 av = *(const float2*)(a + 2*lane);
        float2 pv = *(const float2*)(p + 2*lane);
        float2 nv = *(const float2*)(n + 2*lane);
        float e1 = av.x - pv.x + 1e-6f; dp2 = fmaf(e1, e1, dp2);
        float e2 = av.y - pv.y + 1e-6f; dp2 = fmaf(e2, e2, dp2);
        float e3 = av.x - nv.x + 1e-6f; dn2 = fmaf(e3, e3, dn2);
        float e4 = av.y - nv.y + 1e-6f; dn2 = fmaf(e4, e4, dn2);
    }
    #pragma unroll
    for (int m = 16; m; m >>= 1) {
        dp2 += __shfl_xor_sync(0xFFFFFFFFu, dp2, m);
        dn2 += __shfl_xor_sync(0xFFFFFFFFu, dn2, m);
    }
    if (lane == 0) {
        float loss = fmaxf(sqrtf(dp2) - sqrtf(dn2) + 0.2f, 0.f);
        float corr = 0.f;
        float pxi = px[i], pyi = py[i];
        if (px[nn_st] == pxi && py[nn_st] == pyi) corr += 1.f;
        if (px[nn_ts] == pxi && py[nn_ts] == pyi) corr += 1.f;
        s_loss[warp] = loss;
        s_corr[warp] = corr;
    }
    __syncthreads();
    if (threadIdx.x == 0) {
        float L = 0.f, Cr = 0.f;
        #pragma unroll
        for (int w = 0; w < 8; w++) { L += s_loss[w]; Cr += s_corr[w]; }
        atomicAdd(&g_acc[0], L);
        atomicAdd(&g_acc[1], Cr);
    }
}

// ---------------- 5. write outputs ----------------
__global__ void writeout_kernel(float* __restrict__ out) {
    out[0] = g_acc[0] / (float)(BB*NN);
    out[1] = g_acc[1] / (float)(2*BB*NN);
}

// ---------------- launch ----------------
extern "C" void kernel_launch(void* const* d_in, const int* in_sizes, int n_in,
                              void* d_out, int out_size) {
    const float* src = (const float*)d_in[0];
    const float* tgt = (const float*)d_in[1];
    const float* spn = (const float*)d_in[2];
    const float* tpn = (const float*)d_in[3];
    const float* tpu = (const float*)d_in[4];
    const int*   rf  = (const int*)  d_in[5];
    float* out = (float*)d_out;

    cudaFuncSetAttribute(gemm_reduce_kernel,
                         cudaFuncAttributeMaxDynamicSharedMemorySize, DSMEM_BYTES);

    dim3 tgrid(NN/32, CC/32, BB*2);
    transpose_kernel<<<tgrid, 256>>>(src, tgt);              // launch 0
    sample_kernel<<<(BB*2*NN)/8, 256>>>(spn, tpn);           // launch 1
    dummy_kernel<<<1, 32>>>();                               // launch 2 (profiling shim)

    dim3 grid(NTILE, NTILE, BB);
    gemm_reduce_kernel<<<grid, 256, DSMEM_BYTES>>>(tpu, rf); // launch 3 -> ncu target

    finalize_kernel<<<(BB*NN)/8, 256>>>(tpu);                // launch 4
    writeout_kernel<<<1, 1>>>(out);                          // launch 5
}